// round 10
// baseline (speedup 1.0000x reference)
#include <cuda_runtime.h>
#include <cuda_fp16.h>
#include <math.h>
#include <stdint.h>

// Problem dims (fixed)
#define B_SZ 32768
#define H_SZ 896
#define S_SZ 448
#define Q_SZ 256
#define H3   2688
#define S3   1344

// ---------------------------------------------------------------------------
// Scratch (device globals; allocation-free per harness rules)
// ---------------------------------------------------------------------------
__device__ __half g_Ah [(size_t)B_SZ * H_SZ];    // fp16 prev_hidden
__device__ __half g_hA [(size_t)B_SZ * H_SZ];    // fp16 hidden
__device__ __half g_hc [(size_t)B_SZ * S_SZ];
__device__ __half g_hf [(size_t)B_SZ * S_SZ];
__device__ __half g_RWt[(size_t)H3 * H_SZ];      // R_W^T, gate-interleaved rows
__device__ __half g_O1t[S_SZ * S_SZ];
__device__ __half g_O2t[Q_SZ * S_SZ];
__device__ __half g_O3t[S_SZ * S_SZ];
__device__ __half g_O4t[Q_SZ * S_SZ];

// ---------------------------------------------------------------------------
// Helpers (non-arch-specific PTX only: must assemble for plain sm_103)
// ---------------------------------------------------------------------------
__device__ __forceinline__ uint32_t smem_u32(const void* p) {
    uint32_t a;
    asm("{ .reg .u64 t; cvta.to.shared.u64 t, %1; cvt.u32.u64 %0, t; }" : "=r"(a) : "l"(p));
    return a;
}
__device__ __forceinline__ void cp_async16(uint32_t s, const void* g) {
    asm volatile("cp.async.cg.shared.global [%0], [%1], 16;\n" :: "r"(s), "l"(g));
}
__device__ __forceinline__ void cp_async16_pred(uint32_t s, const void* g, int sz) {
    asm volatile("cp.async.cg.shared.global [%0], [%1], 16, %2;\n"
                 :: "r"(s), "l"(g), "r"(sz));
}
#define CP_COMMIT()  asm volatile("cp.async.commit_group;\n" ::)
#define CP_WAIT(n)   asm volatile("cp.async.wait_group %0;\n" :: "n"(n))

__device__ __forceinline__ void mma_16816(float* d, const uint32_t* a, const uint32_t* b) {
    asm volatile(
        "mma.sync.aligned.m16n8k16.row.col.f32.f16.f16.f32 "
        "{%0,%1,%2,%3}, {%4,%5,%6,%7}, {%8,%9}, {%0,%1,%2,%3};"
        : "+f"(d[0]), "+f"(d[1]), "+f"(d[2]), "+f"(d[3])
        : "r"(a[0]), "r"(a[1]), "r"(a[2]), "r"(a[3]), "r"(b[0]), "r"(b[1]));
}

#define PW 36                     // words per smem row: 64 halves (128B) + 16B pad

// ===========================================================================
// FUSED GEMM1 + GRU:  for CTA tile (128 rows x 96 gate-cols = 32 h-triples)
//   acc = Ah[128,896] @ RWt[96 rows,896]^T   (RWt rows are (3h+g)-permuted)
//   then gate math -> hidden (fp32) + hA (fp16), no Rh scratch.
// 128 threads = 4 warps (2x2), warp tile 64x48, BK=64 fp16.
// ===========================================================================
#define F_AW (128 * PW)           // A words per buffer (4608)
#define F_BW (96 * PW)            // B words per buffer (3456)
#define F_BUFW (F_AW + F_BW)      // 8064 words per buffer

__global__ void __launch_bounds__(128, 2)
gemm_gru(const __half* __restrict__ Ah,       // [B,H] fp16 prev_hidden
         const __half* __restrict__ RWt,      // [2688,896] permuted fp16
         const float* __restrict__ prev_h,    // [B,H] fp32
         const float* __restrict__ prev_y,    // [B,2]
         const float* __restrict__ ccoarse,   // [B,1]
         const float* __restrict__ Icw,       // [2,3S]
         const float* __restrict__ Ifw,       // [3,3S]
         const float* __restrict__ bu, const float* __restrict__ br,
         const float* __restrict__ be,
         float* __restrict__ hidden, __half* __restrict__ hA)
{
    extern __shared__ uint32_t smw[];
    const int tid = threadIdx.x;
    const int lane = tid & 31, w = tid >> 5;
    const int wr = w >> 1, wc = w & 1;        // 2x2 warps; warp tile 64x48
    const int lq = lane >> 2, ln = lane & 3;

    const int rowBase = blockIdx.y * 128;
    const int colBase = blockIdx.x * 96;      // gate-col base (= 3 * h0)

    const uint32_t sBase = smem_u32(smw);

    // A: 128 rows x 8 chunks = 1024, 8/thread ; B: 96 rows x 8 = 768, 6/thread
    const int r0 = tid >> 3, c16 = tid & 7;
    const uint32_t dstOff = (uint32_t)((r0 * PW + c16 * 4) * 4);
    const __half* Abase = Ah + (size_t)(rowBase + r0) * H_SZ + c16 * 8;
    const __half* Bbase = RWt + (size_t)(colBase + r0) * H_SZ + c16 * 8;

    auto load_tile = [&](int buf, int it) {
        const int kb = it * 64;
        const uint32_t base = sBase + (uint32_t)(buf * F_BUFW * 4);
        #pragma unroll
        for (int i = 0; i < 8; ++i)
            cp_async16(base + dstOff + (uint32_t)(i * 16 * PW * 4),
                       Abase + kb + (size_t)(i * 16) * H_SZ);
        #pragma unroll
        for (int i = 0; i < 6; ++i)
            cp_async16(base + (uint32_t)(F_AW * 4) + dstOff + (uint32_t)(i * 16 * PW * 4),
                       Bbase + kb + (size_t)(i * 16) * H_SZ);
        CP_COMMIT();
    };

    float acc[4][6][4];
    #pragma unroll
    for (int i = 0; i < 4; ++i)
        #pragma unroll
        for (int j = 0; j < 6; ++j)
            #pragma unroll
            for (int k = 0; k < 4; ++k) acc[i][j][k] = 0.0f;

    const int nit = H_SZ / 64;    // 14
    load_tile(0, 0);

    for (int it = 0; it < nit; ++it) {
        const int buf = it & 1;
        if (it + 1 < nit) { load_tile(buf ^ 1, it + 1); CP_WAIT(1); }
        else              { CP_WAIT(0); }
        __syncthreads();

        const uint32_t* Ab = smw + buf * F_BUFW;
        const uint32_t* Bb = Ab + F_AW;

        #pragma unroll
        for (int s = 0; s < 4; ++s) {
            const int k8 = s * 8;
            uint32_t a[4][4], b[6][2];
            #pragma unroll
            for (int mf = 0; mf < 4; ++mf) {
                const int m = wr * 64 + mf * 16 + lq;
                a[mf][0] = Ab[m * PW + k8 + ln];
                a[mf][1] = Ab[(m + 8) * PW + k8 + ln];
                a[mf][2] = Ab[m * PW + k8 + ln + 4];
                a[mf][3] = Ab[(m + 8) * PW + k8 + ln + 4];
            }
            #pragma unroll
            for (int nf = 0; nf < 6; ++nf) {
                const int n = wc * 48 + nf * 8 + lq;
                b[nf][0] = Bb[n * PW + k8 + ln];
                b[nf][1] = Bb[n * PW + k8 + ln + 4];
            }
            #pragma unroll
            for (int mf = 0; mf < 4; ++mf)
                #pragma unroll
                for (int nf = 0; nf < 6; ++nf)
                    mma_16816(acc[mf][nf], a[mf], b[nf]);
        }
        __syncthreads();
    }

    // ---- phase 1: acc -> smem tile st[128][97] ----
    float* st = reinterpret_cast<float*>(smw);
    #pragma unroll
    for (int nf = 0; nf < 6; ++nf) {
        const int col = wc * 48 + nf * 8 + ln * 2;
        #pragma unroll
        for (int mf = 0; mf < 4; ++mf) {
            const int row = wr * 64 + mf * 16 + lq;
            st[row * 97 + col]       = acc[mf][nf][0];
            st[row * 97 + col + 1]   = acc[mf][nf][1];
            st[(row + 8) * 97 + col]     = acc[mf][nf][2];
            st[(row + 8) * 97 + col + 1] = acc[mf][nf][3];
        }
    }
    __syncthreads();

    // ---- phase 2: gate math. warp w -> rows [32w,32w+32), lane -> h' ----
    const int h = blockIdx.x * 32 + lane;     // global h for this lane
    float cu0, cu1, cu2, cr0, cr1, cr2, ce0, ce1, ce2;
    if (h < S_SZ) {
        cu0 = Icw[h];            cu1 = Icw[S3 + h];            cu2 = 0.0f;
        cr0 = Icw[S_SZ + h];     cr1 = Icw[S3 + S_SZ + h];     cr2 = 0.0f;
        ce0 = Icw[2 * S_SZ + h]; ce1 = Icw[S3 + 2 * S_SZ + h]; ce2 = 0.0f;
    } else {
        const int hh = h - S_SZ;
        cu0 = Ifw[hh];            cu1 = Ifw[S3 + hh];            cu2 = Ifw[2 * S3 + hh];
        cr0 = Ifw[S_SZ + hh];     cr1 = Ifw[S3 + S_SZ + hh];     cr2 = Ifw[2 * S3 + S_SZ + hh];
        ce0 = Ifw[2 * S_SZ + hh]; ce1 = Ifw[S3 + 2 * S_SZ + hh]; ce2 = Ifw[2 * S3 + 2 * S_SZ + hh];
    }
    const float buh = bu[h], brh = br[h], beh = be[h];

    #pragma unroll 4
    for (int r = 0; r < 32; ++r) {
        const int row = w * 32 + r;
        const int b = rowBase + row;
        const float py0 = prev_y[2 * b], py1 = prev_y[2 * b + 1];
        const float cc = ccoarse[b];

        const float Ru = st[row * 97 + 3 * lane];
        const float Rr = st[row * 97 + 3 * lane + 1];
        const float Re = st[row * 97 + 3 * lane + 2];

        const float Iu = py0 * cu0 + py1 * cu1 + cc * cu2;
        const float Ir = py0 * cr0 + py1 * cr1 + cc * cr2;
        const float Ie = py0 * ce0 + py1 * ce1 + cc * ce2;

        const float u  = 1.0f / (1.0f + expf(-(Ru + Iu + buh)));
        const float rr = 1.0f / (1.0f + expf(-(Rr + Ir + brh)));
        const float e  = tanhf(rr * Re + Ie + beh);

        const float ph = prev_h[(size_t)b * H_SZ + h];
        const float hv = u * ph + (1.0f - u) * e;
        hidden[(size_t)b * H_SZ + h] = hv;
        hA[(size_t)b * H_SZ + h] = __float2half_rn(hv);
    }
}

// ===========================================================================
// Generic fp16 GEMM for the output heads (unchanged from R9)
// ===========================================================================
#define MATW (128 * PW)

template <int EPI, int HOUT, int DUAL>
__global__ void __launch_bounds__(128, 2)
hgemm(const __half* __restrict__ A0, const __half* __restrict__ A1, int lda,
      const __half* __restrict__ B0, const __half* __restrict__ B1, int ldb,
      const float* __restrict__ bias0, const float* __restrict__ bias1,
      void* __restrict__ C0v, void* __restrict__ C1v, int ldc, int N, int K)
{
    extern __shared__ uint32_t smw[];
    const __half* A    = (DUAL && blockIdx.z) ? A1 : A0;
    const __half* Bt   = (DUAL && blockIdx.z) ? B1 : B0;
    const float*  bias = (DUAL && blockIdx.z) ? bias1 : bias0;
    void*         Cv   = (DUAL && blockIdx.z) ? C1v : C0v;

    const int tid = threadIdx.x;
    const int lane = tid & 31, w = tid >> 5;
    const int wr = w >> 1, wc = w & 1;
    const int lq = lane >> 2, ln = lane & 3;

    const int rowBase = blockIdx.y * 128;
    const int colBase = blockIdx.x * 128;

    const uint32_t sBase = smem_u32(smw);
    const int r0 = tid >> 3, c16 = tid & 7;
    const uint32_t dstOff = (uint32_t)((r0 * PW + c16 * 4) * 4);
    const __half* Abase = A + (size_t)(rowBase + r0) * lda + c16 * 8;

    auto load_tile = [&](int buf, int it) {
        const int kb = it * 64;
        const uint32_t base = sBase + (uint32_t)(buf * 2 * MATW * 4);
        #pragma unroll
        for (int i = 0; i < 8; ++i)
            cp_async16(base + dstOff + (uint32_t)(i * 16 * PW * 4),
                       Abase + kb + (size_t)(i * 16) * lda);
        #pragma unroll
        for (int i = 0; i < 8; ++i) {
            const int bn = colBase + r0 + 16 * i;
            const int sz = (bn < N) ? 16 : 0;
            const __half* gp = Bt + (size_t)(sz ? bn : 0) * ldb + c16 * 8 + kb;
            cp_async16_pred(base + (uint32_t)(MATW * 4) + dstOff + (uint32_t)(i * 16 * PW * 4),
                            gp, sz);
        }
        CP_COMMIT();
    };

    float acc[4][8][4];
    #pragma unroll
    for (int i = 0; i < 4; ++i)
        #pragma unroll
        for (int j = 0; j < 8; ++j)
            #pragma unroll
            for (int k = 0; k < 4; ++k) acc[i][j][k] = 0.0f;

    const int nit = K >> 6;
    load_tile(0, 0);

    for (int it = 0; it < nit; ++it) {
        const int buf = it & 1;
        if (it + 1 < nit) { load_tile(buf ^ 1, it + 1); CP_WAIT(1); }
        else              { CP_WAIT(0); }
        __syncthreads();

        const uint32_t* Ab = smw + buf * 2 * MATW;
        const uint32_t* Bb = Ab + MATW;

        #pragma unroll
        for (int s = 0; s < 4; ++s) {
            const int k8 = s * 8;
            uint32_t a[4][4], b[8][2];
            #pragma unroll
            for (int mf = 0; mf < 4; ++mf) {
                const int m = wr * 64 + mf * 16 + lq;
                a[mf][0] = Ab[m * PW + k8 + ln];
                a[mf][1] = Ab[(m + 8) * PW + k8 + ln];
                a[mf][2] = Ab[m * PW + k8 + ln + 4];
                a[mf][3] = Ab[(m + 8) * PW + k8 + ln + 4];
            }
            #pragma unroll
            for (int nf = 0; nf < 8; ++nf) {
                const int n = wc * 64 + nf * 8 + lq;
                b[nf][0] = Bb[n * PW + k8 + ln];
                b[nf][1] = Bb[n * PW + k8 + ln + 4];
            }
            #pragma unroll
            for (int mf = 0; mf < 4; ++mf)
                #pragma unroll
                for (int nf = 0; nf < 8; ++nf)
                    mma_16816(acc[mf][nf], a[mf], b[nf]);
        }
        __syncthreads();
    }

    #pragma unroll
    for (int nf = 0; nf < 8; ++nf) {
        const int col = colBase + wc * 64 + nf * 8 + ln * 2;
        if (col < N) {
            float2 bv = make_float2(0.0f, 0.0f);
            if (EPI) bv = *reinterpret_cast<const float2*>(bias + col);
            #pragma unroll
            for (int mf = 0; mf < 4; ++mf) {
                const int row = rowBase + wr * 64 + mf * 16 + lq;
                float2 v0 = make_float2(acc[mf][nf][0], acc[mf][nf][1]);
                float2 v1 = make_float2(acc[mf][nf][2], acc[mf][nf][3]);
                if (EPI) {
                    v0.x += bv.x; v0.y += bv.y; v1.x += bv.x; v1.y += bv.y;
                    if (EPI == 1) {
                        v0.x = fmaxf(v0.x, 0.0f); v0.y = fmaxf(v0.y, 0.0f);
                        v1.x = fmaxf(v1.x, 0.0f); v1.y = fmaxf(v1.y, 0.0f);
                    }
                }
                if (HOUT) {
                    __half* Ch = (__half*)Cv;
                    *reinterpret_cast<__half2*>(Ch + (size_t)row * ldc + col) =
                        __floats2half2_rn(v0.x, v0.y);
                    *reinterpret_cast<__half2*>(Ch + (size_t)(row + 8) * ldc + col) =
                        __floats2half2_rn(v1.x, v1.y);
                } else {
                    float* Cf = (float*)Cv;
                    *reinterpret_cast<float2*>(Cf + (size_t)row * ldc + col) = v0;
                    *reinterpret_cast<float2*>(Cf + (size_t)(row + 8) * ldc + col) = v1;
                }
            }
        }
    }
}

// ---------------------------------------------------------------------------
// Prep: fp32 -> fp16 bulk convert
// ---------------------------------------------------------------------------
__global__ void f2h(const float4* __restrict__ in, __half2* __restrict__ out, int n4) {
    const int i = blockIdx.x * blockDim.x + threadIdx.x;
    if (i < n4) {
        float4 v = in[i];
        out[2 * i]     = __floats2half2_rn(v.x, v.y);
        out[2 * i + 1] = __floats2half2_rn(v.z, v.w);
    }
}

// Weight prep: [K,N] fp32 -> [N,K] fp16 (dual via z). PERM: gate-interleave
// output rows (n = g*896+h  ->  3*h+g) for the fused GEMM1.
template <int PERM>
__global__ void transpose_h(const float* __restrict__ in0, const float* __restrict__ in1,
                            __half* __restrict__ out0, __half* __restrict__ out1,
                            int K, int N) {
    __shared__ float t[32][33];
    const float* in  = blockIdx.z ? in1 : in0;
    __half*      out = blockIdx.z ? out1 : out0;
    const int n0 = blockIdx.x * 32, k0 = blockIdx.y * 32;
    const int tx = threadIdx.x, ty = threadIdx.y;   // 32 x 8
    #pragma unroll
    for (int j = 0; j < 32; j += 8)
        t[ty + j][tx] = in[(size_t)(k0 + ty + j) * N + n0 + tx];
    __syncthreads();
    #pragma unroll
    for (int j = 0; j < 32; j += 8) {
        int n = n0 + ty + j;
        if (PERM) { const int g = n / H_SZ, h = n - g * H_SZ; n = 3 * h + g; }
        out[(size_t)n * K + k0 + tx] = __float2half_rn(t[tx][ty + j]);
    }
}

// ---------------------------------------------------------------------------
// Launch
// ---------------------------------------------------------------------------
extern "C" void kernel_launch(void* const* d_in, const int* in_sizes, int n_in,
                              void* d_out, int out_size)
{
    const float* prev_y  = (const float*)d_in[0];
    const float* prev_h  = (const float*)d_in[1];
    const float* ccoarse = (const float*)d_in[2];
    const float* R_W     = (const float*)d_in[3];
    const float* Icw     = (const float*)d_in[4];
    const float* Ifw     = (const float*)d_in[5];
    const float* O1_W    = (const float*)d_in[6];
    const float* O1_b    = (const float*)d_in[7];
    const float* O2_W    = (const float*)d_in[8];
    const float* O2_b    = (const float*)d_in[9];
    const float* O3_W    = (const float*)d_in[10];
    const float* O3_b    = (const float*)d_in[11];
    const float* O4_W    = (const float*)d_in[12];
    const float* O4_b    = (const float*)d_in[13];
    const float* bu      = (const float*)d_in[14];
    const float* br      = (const float*)d_in[15];
    const float* be      = (const float*)d_in[16];

    float* out        = (float*)d_out;
    float* out_coarse = out;
    float* out_fine   = out + (size_t)B_SZ * Q_SZ;
    float* hidden     = out + (size_t)2 * B_SZ * Q_SZ;

    __half *Ah, *hA, *hc, *hf, *RWt, *O1t, *O2t, *O3t, *O4t;
    cudaGetSymbolAddress((void**)&Ah,  g_Ah);
    cudaGetSymbolAddress((void**)&hA,  g_hA);
    cudaGetSymbolAddress((void**)&hc,  g_hc);
    cudaGetSymbolAddress((void**)&hf,  g_hf);
    cudaGetSymbolAddress((void**)&RWt, g_RWt);
    cudaGetSymbolAddress((void**)&O1t, g_O1t);
    cudaGetSymbolAddress((void**)&O2t, g_O2t);
    cudaGetSymbolAddress((void**)&O3t, g_O3t);
    cudaGetSymbolAddress((void**)&O4t, g_O4t);

    const int SMB_F = F_BUFW * 2 * 4;   // fused: 64512 B
    const int SMB_H = 4 * MATW * 4;     // heads: 73728 B
    cudaFuncSetAttribute(gemm_gru,       cudaFuncAttributeMaxDynamicSharedMemorySize, SMB_F);
    cudaFuncSetAttribute(hgemm<1, 1, 1>, cudaFuncAttributeMaxDynamicSharedMemorySize, SMB_H);
    cudaFuncSetAttribute(hgemm<2, 0, 1>, cudaFuncAttributeMaxDynamicSharedMemorySize, SMB_H);

    // --- prep: 4 launches ---
    const int n4 = B_SZ * H_SZ / 4;
    f2h<<<(n4 + 255) / 256, 256>>>((const float4*)prev_h, (__half2*)Ah, n4);
    transpose_h<1><<<dim3(H3 / 32, H_SZ / 32, 1), dim3(32, 8)>>>(R_W, R_W, RWt, RWt, H_SZ, H3);
    transpose_h<0><<<dim3(S_SZ / 32, S_SZ / 32, 2), dim3(32, 8)>>>(O1_W, O3_W, O1t, O3t, S_SZ, S_SZ);
    transpose_h<0><<<dim3(Q_SZ / 32, S_SZ / 32, 2), dim3(32, 8)>>>(O2_W, O4_W, O2t, O4t, S_SZ, Q_SZ);

    const int MT = B_SZ / 128;   // 256 M-tiles

    // 1) Fused: GEMM1 + GRU gates -> hidden (fp32) + hA (fp16). No Rh scratch.
    gemm_gru<<<dim3(H3 / 96, MT), 128, SMB_F>>>(
        Ah, RWt, prev_h, prev_y, ccoarse, Icw, Ifw, bu, br, be, hidden, hA);
    // 2+3) hc = relu(hidden_c @ O1 + b1); hf = relu(hidden_f @ O3 + b3)  [fp16 out]
    hgemm<1, 1, 1><<<dim3(4, MT, 2), 128, SMB_H>>>(
        hA, hA + S_SZ, H_SZ, O1t, O3t, S_SZ, O1_b, O3_b,
        hc, hf, S_SZ, S_SZ, S_SZ);
    // 4+5) out_coarse = hc @ O2 + b2; out_fine = hf @ O4 + b4  [fp32 out]
    hgemm<2, 0, 1><<<dim3(2, MT, 2), 128, SMB_H>>>(
        hc, hf, S_SZ, O2t, O4t, S_SZ, O2_b, O4_b,
        out_coarse, out_fine, Q_SZ, Q_SZ, S_SZ);
}

// round 11
// speedup vs baseline: 1.1896x; 1.1896x over previous
#include <cuda_runtime.h>
#include <cuda_fp16.h>
#include <math.h>
#include <stdint.h>

// Problem dims (fixed)
#define B_SZ 32768
#define H_SZ 896
#define S_SZ 448
#define Q_SZ 256
#define H3   2688
#define S3   1344

// ---------------------------------------------------------------------------
// Scratch (device globals; allocation-free per harness rules)
// ---------------------------------------------------------------------------
__device__ __half g_Rh [(size_t)B_SZ * H3];      // R_hidden fp16 (halved traffic)
__device__ __half g_Ah [(size_t)B_SZ * H_SZ];    // fp16 prev_hidden
__device__ __half g_hA [(size_t)B_SZ * H_SZ];    // fp16 hidden
__device__ __half g_hc [(size_t)B_SZ * S_SZ];    // fp16 relu head intermediates
__device__ __half g_hf [(size_t)B_SZ * S_SZ];
__device__ __half g_RWt[(size_t)H3 * H_SZ];      // fp16 transposed weights
__device__ __half g_O1t[S_SZ * S_SZ];
__device__ __half g_O2t[Q_SZ * S_SZ];
__device__ __half g_O3t[S_SZ * S_SZ];
__device__ __half g_O4t[Q_SZ * S_SZ];

// ---------------------------------------------------------------------------
// Helpers (non-arch-specific PTX only: must assemble for plain sm_103)
// ---------------------------------------------------------------------------
__device__ __forceinline__ uint32_t smem_u32(const void* p) {
    uint32_t a;
    asm("{ .reg .u64 t; cvta.to.shared.u64 t, %1; cvt.u32.u64 %0, t; }" : "=r"(a) : "l"(p));
    return a;
}
__device__ __forceinline__ void cp_async16(uint32_t s, const void* g) {
    asm volatile("cp.async.cg.shared.global [%0], [%1], 16;\n" :: "r"(s), "l"(g));
}
__device__ __forceinline__ void cp_async16_pred(uint32_t s, const void* g, int sz) {
    asm volatile("cp.async.cg.shared.global [%0], [%1], 16, %2;\n"
                 :: "r"(s), "l"(g), "r"(sz));
}
#define CP_COMMIT()  asm volatile("cp.async.commit_group;\n" ::)
#define CP_WAIT(n)   asm volatile("cp.async.wait_group %0;\n" :: "n"(n))

__device__ __forceinline__ void mma_16816(float* d, const uint32_t* a, const uint32_t* b) {
    asm volatile(
        "mma.sync.aligned.m16n8k16.row.col.f32.f16.f16.f32 "
        "{%0,%1,%2,%3}, {%4,%5,%6,%7}, {%8,%9}, {%0,%1,%2,%3};"
        : "+f"(d[0]), "+f"(d[1]), "+f"(d[2]), "+f"(d[3])
        : "r"(a[0]), "r"(a[1]), "r"(a[2]), "r"(a[3]), "r"(b[0]), "r"(b[1]));
}

// ---------------------------------------------------------------------------
// fp16 mma.sync GEMM: C[M,N] = A[M,K] @ Bt[N,K]^T (+bias)(+relu)
// CTA 128x128, BK=64 (fp16), 128 thr = 4 warps (2x2), warp tile 64x64.
// EPI: 0=none, 1=bias+relu, 2=bias.  HOUT: 1 = __half C, 0 = float C.
// DUAL: blockIdx.z selects problem set.
// ---------------------------------------------------------------------------
#define PW   36                   // words (4B) per smem row: 64 halves + 16B pad
#define MATW (128 * PW)           // words per matrix per buffer

template <int EPI, int HOUT, int DUAL>
__global__ void __launch_bounds__(128, 2)
hgemm(const __half* __restrict__ A0, const __half* __restrict__ A1, int lda,
      const __half* __restrict__ B0, const __half* __restrict__ B1, int ldb,
      const float* __restrict__ bias0, const float* __restrict__ bias1,
      void* __restrict__ C0v, void* __restrict__ C1v, int ldc, int N, int K)
{
    extern __shared__ uint32_t smw[];   // [2 buf][A|B][128][PW]
    const __half* A    = (DUAL && blockIdx.z) ? A1 : A0;
    const __half* Bt   = (DUAL && blockIdx.z) ? B1 : B0;
    const float*  bias = (DUAL && blockIdx.z) ? bias1 : bias0;
    void*         Cv   = (DUAL && blockIdx.z) ? C1v : C0v;

    const int tid = threadIdx.x;
    const int lane = tid & 31, w = tid >> 5;
    const int wr = w >> 1, wc = w & 1;        // 2x2 warps, warp tile 64x64
    const int lq = lane >> 2, ln = lane & 3;

    const int rowBase = blockIdx.y * 128;
    const int colBase = blockIdx.x * 128;

    const uint32_t sBase = smem_u32(smw);

    // cp.async: per matrix per iter 128 rows x 128B = 1024 chunks; 8/thread.
    const int r0 = tid >> 3, c16 = tid & 7;           // row 0..15, 16B-col 0..7
    const uint32_t dstOff = (uint32_t)((r0 * PW + c16 * 4) * 4);   // bytes
    const __half* Abase = A + (size_t)(rowBase + r0) * lda + c16 * 8;

    auto load_tile = [&](int buf, int it) {
        const int kb = it * 64;
        const uint32_t base = sBase + (uint32_t)(buf * 2 * MATW * 4);
        #pragma unroll
        for (int i = 0; i < 8; ++i)
            cp_async16(base + dstOff + (uint32_t)(i * 16 * PW * 4),
                       Abase + kb + (size_t)(i * 16) * lda);
        #pragma unroll
        for (int i = 0; i < 8; ++i) {
            const int bn = colBase + r0 + 16 * i;
            const int sz = (bn < N) ? 16 : 0;
            const __half* gp = Bt + (size_t)(sz ? bn : 0) * ldb + c16 * 8 + kb;
            cp_async16_pred(base + (uint32_t)(MATW * 4) + dstOff + (uint32_t)(i * 16 * PW * 4),
                            gp, sz);
        }
        CP_COMMIT();
    };

    float acc[4][8][4];
    #pragma unroll
    for (int i = 0; i < 4; ++i)
        #pragma unroll
        for (int j = 0; j < 8; ++j)
            #pragma unroll
            for (int k = 0; k < 4; ++k) acc[i][j][k] = 0.0f;

    const int nit = K >> 6;
    load_tile(0, 0);

    for (int it = 0; it < nit; ++it) {
        const int buf = it & 1;
        if (it + 1 < nit) { load_tile(buf ^ 1, it + 1); CP_WAIT(1); }
        else              { CP_WAIT(0); }
        __syncthreads();

        const uint32_t* Ab = smw + buf * 2 * MATW;
        const uint32_t* Bb = Ab + MATW;

        #pragma unroll
        for (int s = 0; s < 4; ++s) {          // 4 x K=16 steps
            const int k8 = s * 8;
            uint32_t a[4][4], b[8][2];
            #pragma unroll
            for (int mf = 0; mf < 4; ++mf) {
                const int m = wr * 64 + mf * 16 + lq;
                a[mf][0] = Ab[m * PW + k8 + ln];
                a[mf][1] = Ab[(m + 8) * PW + k8 + ln];
                a[mf][2] = Ab[m * PW + k8 + ln + 4];
                a[mf][3] = Ab[(m + 8) * PW + k8 + ln + 4];
            }
            #pragma unroll
            for (int nf = 0; nf < 8; ++nf) {
                const int n = wc * 64 + nf * 8 + lq;
                b[nf][0] = Bb[n * PW + k8 + ln];
                b[nf][1] = Bb[n * PW + k8 + ln + 4];
            }
            #pragma unroll
            for (int mf = 0; mf < 4; ++mf)
                #pragma unroll
                for (int nf = 0; nf < 8; ++nf)
                    mma_16816(acc[mf][nf], a[mf], b[nf]);
        }
        __syncthreads();
    }

    // ---- epilogue ----
    #pragma unroll
    for (int nf = 0; nf < 8; ++nf) {
        const int col = colBase + wc * 64 + nf * 8 + ln * 2;
        if (col < N) {
            float2 bv = make_float2(0.0f, 0.0f);
            if (EPI) bv = *reinterpret_cast<const float2*>(bias + col);
            #pragma unroll
            for (int mf = 0; mf < 4; ++mf) {
                const int row = rowBase + wr * 64 + mf * 16 + lq;
                float2 v0 = make_float2(acc[mf][nf][0], acc[mf][nf][1]);
                float2 v1 = make_float2(acc[mf][nf][2], acc[mf][nf][3]);
                if (EPI) {
                    v0.x += bv.x; v0.y += bv.y; v1.x += bv.x; v1.y += bv.y;
                    if (EPI == 1) {
                        v0.x = fmaxf(v0.x, 0.0f); v0.y = fmaxf(v0.y, 0.0f);
                        v1.x = fmaxf(v1.x, 0.0f); v1.y = fmaxf(v1.y, 0.0f);
                    }
                }
                if (HOUT) {
                    __half* Ch = (__half*)Cv;
                    *reinterpret_cast<__half2*>(Ch + (size_t)row * ldc + col) =
                        __floats2half2_rn(v0.x, v0.y);
                    *reinterpret_cast<__half2*>(Ch + (size_t)(row + 8) * ldc + col) =
                        __floats2half2_rn(v1.x, v1.y);
                } else {
                    float* Cf = (float*)Cv;
                    *reinterpret_cast<float2*>(Cf + (size_t)row * ldc + col) = v0;
                    *reinterpret_cast<float2*>(Cf + (size_t)(row + 8) * ldc + col) = v1;
                }
            }
        }
    }
}

// ---------------------------------------------------------------------------
// Prep: fp32 -> fp16 bulk convert
// ---------------------------------------------------------------------------
__global__ void f2h(const float4* __restrict__ in, __half2* __restrict__ out, int n4) {
    const int i = blockIdx.x * blockDim.x + threadIdx.x;
    if (i < n4) {
        float4 v = in[i];
        out[2 * i]     = __floats2half2_rn(v.x, v.y);
        out[2 * i + 1] = __floats2half2_rn(v.z, v.w);
    }
}

// Weight prep: [K,N] fp32 row-major -> [N,K] fp16 row-major (dual via blockIdx.z)
__global__ void transpose_h(const float* __restrict__ in0, const float* __restrict__ in1,
                            __half* __restrict__ out0, __half* __restrict__ out1,
                            int K, int N) {
    __shared__ float t[32][33];
    const float* in  = blockIdx.z ? in1 : in0;
    __half*      out = blockIdx.z ? out1 : out0;
    const int n0 = blockIdx.x * 32, k0 = blockIdx.y * 32;
    const int tx = threadIdx.x, ty = threadIdx.y;   // 32 x 8
    #pragma unroll
    for (int j = 0; j < 32; j += 8)
        t[ty + j][tx] = in[(size_t)(k0 + ty + j) * N + n0 + tx];
    __syncthreads();
    #pragma unroll
    for (int j = 0; j < 32; j += 8)
        out[(size_t)(n0 + ty + j) * K + k0 + tx] = __float2half_rn(t[tx][ty + j]);
}

// ---------------------------------------------------------------------------
// GRU gate elementwise; Rh is fp16; emits fp32 hidden + fp16 copy
// ---------------------------------------------------------------------------
__global__ void gru_elem(const __half* __restrict__ Rh, const float* __restrict__ prev_h,
                         const float* __restrict__ prev_y, const float* __restrict__ ccoarse,
                         const float* __restrict__ Icw, const float* __restrict__ Ifw,
                         const float* __restrict__ bu, const float* __restrict__ br,
                         const float* __restrict__ be,
                         float* __restrict__ hidden, __half* __restrict__ hA) {
    const int idx = blockIdx.x * blockDim.x + threadIdx.x;
    if (idx >= B_SZ * H_SZ) return;
    const int b = idx / H_SZ;
    const int h = idx - b * H_SZ;

    const float py0 = prev_y[2 * b], py1 = prev_y[2 * b + 1];
    float Iu, Ir, Ie;
    if (h < S_SZ) {
        Iu = py0 * Icw[h]            + py1 * Icw[S3 + h];
        Ir = py0 * Icw[S_SZ + h]     + py1 * Icw[S3 + S_SZ + h];
        Ie = py0 * Icw[2 * S_SZ + h] + py1 * Icw[S3 + 2 * S_SZ + h];
    } else {
        const int hh = h - S_SZ;
        const float cc = ccoarse[b];
        Iu = py0 * Ifw[hh]            + py1 * Ifw[S3 + hh]            + cc * Ifw[2 * S3 + hh];
        Ir = py0 * Ifw[S_SZ + hh]     + py1 * Ifw[S3 + S_SZ + hh]     + cc * Ifw[2 * S3 + S_SZ + hh];
        Ie = py0 * Ifw[2 * S_SZ + hh] + py1 * Ifw[S3 + 2 * S_SZ + hh] + cc * Ifw[2 * S3 + 2 * S_SZ + hh];
    }
    const __half* r0 = Rh + (size_t)b * H3;
    const float Ru = __half2float(r0[h]);
    const float Rr = __half2float(r0[H_SZ + h]);
    const float Re = __half2float(r0[2 * H_SZ + h]);

    const float u = 1.0f / (1.0f + expf(-(Ru + Iu + bu[h])));
    const float r = 1.0f / (1.0f + expf(-(Rr + Ir + br[h])));
    const float e = tanhf(r * Re + Ie + be[h]);

    const float hv = u * prev_h[idx] + (1.0f - u) * e;
    hidden[idx] = hv;
    hA[idx] = __float2half_rn(hv);
}

// ---------------------------------------------------------------------------
// Launch
// ---------------------------------------------------------------------------
extern "C" void kernel_launch(void* const* d_in, const int* in_sizes, int n_in,
                              void* d_out, int out_size)
{
    const float* prev_y  = (const float*)d_in[0];
    const float* prev_h  = (const float*)d_in[1];
    const float* ccoarse = (const float*)d_in[2];
    const float* R_W     = (const float*)d_in[3];
    const float* Icw     = (const float*)d_in[4];
    const float* Ifw     = (const float*)d_in[5];
    const float* O1_W    = (const float*)d_in[6];
    const float* O1_b    = (const float*)d_in[7];
    const float* O2_W    = (const float*)d_in[8];
    const float* O2_b    = (const float*)d_in[9];
    const float* O3_W    = (const float*)d_in[10];
    const float* O3_b    = (const float*)d_in[11];
    const float* O4_W    = (const float*)d_in[12];
    const float* O4_b    = (const float*)d_in[13];
    const float* bu      = (const float*)d_in[14];
    const float* br      = (const float*)d_in[15];
    const float* be      = (const float*)d_in[16];

    float* out        = (float*)d_out;
    float* out_coarse = out;
    float* out_fine   = out + (size_t)B_SZ * Q_SZ;
    float* hidden     = out + (size_t)2 * B_SZ * Q_SZ;

    __half *Rh, *Ah, *hA, *hc, *hf, *RWt, *O1t, *O2t, *O3t, *O4t;
    cudaGetSymbolAddress((void**)&Rh,  g_Rh);
    cudaGetSymbolAddress((void**)&Ah,  g_Ah);
    cudaGetSymbolAddress((void**)&hA,  g_hA);
    cudaGetSymbolAddress((void**)&hc,  g_hc);
    cudaGetSymbolAddress((void**)&hf,  g_hf);
    cudaGetSymbolAddress((void**)&RWt, g_RWt);
    cudaGetSymbolAddress((void**)&O1t, g_O1t);
    cudaGetSymbolAddress((void**)&O2t, g_O2t);
    cudaGetSymbolAddress((void**)&O3t, g_O3t);
    cudaGetSymbolAddress((void**)&O4t, g_O4t);

    const int SMB = 4 * MATW * 4;   // 73728 bytes dynamic smem
    cudaFuncSetAttribute(hgemm<0, 1, 0>, cudaFuncAttributeMaxDynamicSharedMemorySize, SMB);
    cudaFuncSetAttribute(hgemm<1, 1, 1>, cudaFuncAttributeMaxDynamicSharedMemorySize, SMB);
    cudaFuncSetAttribute(hgemm<2, 0, 1>, cudaFuncAttributeMaxDynamicSharedMemorySize, SMB);

    // --- prep ---
    const int n4 = B_SZ * H_SZ / 4;
    f2h<<<(n4 + 255) / 256, 256>>>((const float4*)prev_h, (__half2*)Ah, n4);
    transpose_h<<<dim3(H3 / 32, H_SZ / 32, 1), dim3(32, 8)>>>(R_W, R_W, RWt, RWt, H_SZ, H3);
    transpose_h<<<dim3(S_SZ / 32, S_SZ / 32, 2), dim3(32, 8)>>>(O1_W, O3_W, O1t, O3t, S_SZ, S_SZ);
    transpose_h<<<dim3(Q_SZ / 32, S_SZ / 32, 2), dim3(32, 8)>>>(O2_W, O4_W, O2t, O4t, S_SZ, Q_SZ);

    const int MT = B_SZ / 128;   // 256 M-tiles

    // 1) Rh = Ah @ RWt^T   (fp16 in, fp16 out — halved scratch traffic)
    hgemm<0, 1, 0><<<dim3(H3 / 128, MT, 1), 128, SMB>>>(
        Ah, nullptr, H_SZ, RWt, nullptr, H_SZ, nullptr, nullptr,
        Rh, nullptr, H3, H3, H_SZ);
    // 2) GRU gates -> hidden (fp32) + fp16 copy
    gru_elem<<<(B_SZ * H_SZ + 255) / 256, 256>>>(Rh, prev_h, prev_y, ccoarse,
                                                 Icw, Ifw, bu, br, be, hidden, hA);
    // 3+4) hc = relu(hidden_c @ O1 + b1); hf = relu(hidden_f @ O3 + b3)  [fp16 out]
    hgemm<1, 1, 1><<<dim3(4, MT, 2), 128, SMB>>>(
        hA, hA + S_SZ, H_SZ, O1t, O3t, S_SZ, O1_b, O3_b,
        hc, hf, S_SZ, S_SZ, S_SZ);
    // 5+6) out_coarse = hc @ O2 + b2; out_fine = hf @ O4 + b4  [fp32 out]
    hgemm<2, 0, 1><<<dim3(2, MT, 2), 128, SMB>>>(
        hc, hf, S_SZ, O2t, O4t, S_SZ, O2_b, O4_b,
        out_coarse, out_fine, Q_SZ, Q_SZ, S_SZ);
}

// round 12
// speedup vs baseline: 1.2740x; 1.0710x over previous
#include <cuda_runtime.h>
#include <cuda_fp16.h>
#include <math.h>
#include <stdint.h>

// Problem dims (fixed)
#define B_SZ 32768
#define H_SZ 896
#define S_SZ 448
#define Q_SZ 256
#define H3   2688
#define S3   1344

// ---------------------------------------------------------------------------
// Scratch (device globals; allocation-free per harness rules)
// ---------------------------------------------------------------------------
__device__ __half g_Rh [(size_t)B_SZ * H3];      // R_hidden fp16
__device__ __half g_Ah [(size_t)B_SZ * H_SZ];    // fp16 prev_hidden
__device__ __half g_hA [(size_t)B_SZ * H_SZ];    // fp16 hidden
__device__ __half g_hc [(size_t)B_SZ * S_SZ];
__device__ __half g_hf [(size_t)B_SZ * S_SZ];
__device__ __half g_RWt[(size_t)H3 * H_SZ];
__device__ __half g_O1t[S_SZ * S_SZ];
__device__ __half g_O2t[Q_SZ * S_SZ];
__device__ __half g_O3t[S_SZ * S_SZ];
__device__ __half g_O4t[Q_SZ * S_SZ];

// ---------------------------------------------------------------------------
// Helpers (non-arch-specific PTX only: must assemble for plain sm_103)
// ---------------------------------------------------------------------------
__device__ __forceinline__ uint32_t smem_u32(const void* p) {
    uint32_t a;
    asm("{ .reg .u64 t; cvta.to.shared.u64 t, %1; cvt.u32.u64 %0, t; }" : "=r"(a) : "l"(p));
    return a;
}
__device__ __forceinline__ void cp_async16(uint32_t s, const void* g) {
    asm volatile("cp.async.cg.shared.global [%0], [%1], 16;\n" :: "r"(s), "l"(g));
}
__device__ __forceinline__ void cp_async16_pred(uint32_t s, const void* g, int sz) {
    asm volatile("cp.async.cg.shared.global [%0], [%1], 16, %2;\n"
                 :: "r"(s), "l"(g), "r"(sz));
}
#define CP_COMMIT()  asm volatile("cp.async.commit_group;\n" ::)
#define CP_WAIT(n)   asm volatile("cp.async.wait_group %0;\n" :: "n"(n))

__device__ __forceinline__ void mma_16816(float* d, const uint32_t* a, const uint32_t* b) {
    asm volatile(
        "mma.sync.aligned.m16n8k16.row.col.f32.f16.f16.f32 "
        "{%0,%1,%2,%3}, {%4,%5,%6,%7}, {%8,%9}, {%0,%1,%2,%3};"
        : "+f"(d[0]), "+f"(d[1]), "+f"(d[2]), "+f"(d[3])
        : "r"(a[0]), "r"(a[1]), "r"(a[2]), "r"(a[3]), "r"(b[0]), "r"(b[1]));
}

// ---------------------------------------------------------------------------
// fp16 mma.sync GEMM (identical to R11 877us version)
// ---------------------------------------------------------------------------
#define PW   36
#define MATW (128 * PW)

template <int EPI, int HOUT, int DUAL>
__global__ void __launch_bounds__(128, 2)
hgemm(const __half* __restrict__ A0, const __half* __restrict__ A1, int lda,
      const __half* __restrict__ B0, const __half* __restrict__ B1, int ldb,
      const float* __restrict__ bias0, const float* __restrict__ bias1,
      void* __restrict__ C0v, void* __restrict__ C1v, int ldc, int N, int K)
{
    extern __shared__ uint32_t smw[];
    const __half* A    = (DUAL && blockIdx.z) ? A1 : A0;
    const __half* Bt   = (DUAL && blockIdx.z) ? B1 : B0;
    const float*  bias = (DUAL && blockIdx.z) ? bias1 : bias0;
    void*         Cv   = (DUAL && blockIdx.z) ? C1v : C0v;

    const int tid = threadIdx.x;
    const int lane = tid & 31, w = tid >> 5;
    const int wr = w >> 1, wc = w & 1;
    const int lq = lane >> 2, ln = lane & 3;

    const int rowBase = blockIdx.y * 128;
    const int colBase = blockIdx.x * 128;

    const uint32_t sBase = smem_u32(smw);
    const int r0 = tid >> 3, c16 = tid & 7;
    const uint32_t dstOff = (uint32_t)((r0 * PW + c16 * 4) * 4);
    const __half* Abase = A + (size_t)(rowBase + r0) * lda + c16 * 8;

    auto load_tile = [&](int buf, int it) {
        const int kb = it * 64;
        const uint32_t base = sBase + (uint32_t)(buf * 2 * MATW * 4);
        #pragma unroll
        for (int i = 0; i < 8; ++i)
            cp_async16(base + dstOff + (uint32_t)(i * 16 * PW * 4),
                       Abase + kb + (size_t)(i * 16) * lda);
        #pragma unroll
        for (int i = 0; i < 8; ++i) {
            const int bn = colBase + r0 + 16 * i;
            const int sz = (bn < N) ? 16 : 0;
            const __half* gp = Bt + (size_t)(sz ? bn : 0) * ldb + c16 * 8 + kb;
            cp_async16_pred(base + (uint32_t)(MATW * 4) + dstOff + (uint32_t)(i * 16 * PW * 4),
                            gp, sz);
        }
        CP_COMMIT();
    };

    float acc[4][8][4];
    #pragma unroll
    for (int i = 0; i < 4; ++i)
        #pragma unroll
        for (int j = 0; j < 8; ++j)
            #pragma unroll
            for (int k = 0; k < 4; ++k) acc[i][j][k] = 0.0f;

    const int nit = K >> 6;
    load_tile(0, 0);

    for (int it = 0; it < nit; ++it) {
        const int buf = it & 1;
        if (it + 1 < nit) { load_tile(buf ^ 1, it + 1); CP_WAIT(1); }
        else              { CP_WAIT(0); }
        __syncthreads();

        const uint32_t* Ab = smw + buf * 2 * MATW;
        const uint32_t* Bb = Ab + MATW;

        #pragma unroll
        for (int s = 0; s < 4; ++s) {
            const int k8 = s * 8;
            uint32_t a[4][4], b[8][2];
            #pragma unroll
            for (int mf = 0; mf < 4; ++mf) {
                const int m = wr * 64 + mf * 16 + lq;
                a[mf][0] = Ab[m * PW + k8 + ln];
                a[mf][1] = Ab[(m + 8) * PW + k8 + ln];
                a[mf][2] = Ab[m * PW + k8 + ln + 4];
                a[mf][3] = Ab[(m + 8) * PW + k8 + ln + 4];
            }
            #pragma unroll
            for (int nf = 0; nf < 8; ++nf) {
                const int n = wc * 64 + nf * 8 + lq;
                b[nf][0] = Bb[n * PW + k8 + ln];
                b[nf][1] = Bb[n * PW + k8 + ln + 4];
            }
            #pragma unroll
            for (int mf = 0; mf < 4; ++mf)
                #pragma unroll
                for (int nf = 0; nf < 8; ++nf)
                    mma_16816(acc[mf][nf], a[mf], b[nf]);
        }
        __syncthreads();
    }

    #pragma unroll
    for (int nf = 0; nf < 8; ++nf) {
        const int col = colBase + wc * 64 + nf * 8 + ln * 2;
        if (col < N) {
            float2 bv = make_float2(0.0f, 0.0f);
            if (EPI) bv = *reinterpret_cast<const float2*>(bias + col);
            #pragma unroll
            for (int mf = 0; mf < 4; ++mf) {
                const int row = rowBase + wr * 64 + mf * 16 + lq;
                float2 v0 = make_float2(acc[mf][nf][0], acc[mf][nf][1]);
                float2 v1 = make_float2(acc[mf][nf][2], acc[mf][nf][3]);
                if (EPI) {
                    v0.x += bv.x; v0.y += bv.y; v1.x += bv.x; v1.y += bv.y;
                    if (EPI == 1) {
                        v0.x = fmaxf(v0.x, 0.0f); v0.y = fmaxf(v0.y, 0.0f);
                        v1.x = fmaxf(v1.x, 0.0f); v1.y = fmaxf(v1.y, 0.0f);
                    }
                }
                if (HOUT) {
                    __half* Ch = (__half*)Cv;
                    *reinterpret_cast<__half2*>(Ch + (size_t)row * ldc + col) =
                        __floats2half2_rn(v0.x, v0.y);
                    *reinterpret_cast<__half2*>(Ch + (size_t)(row + 8) * ldc + col) =
                        __floats2half2_rn(v1.x, v1.y);
                } else {
                    float* Cf = (float*)Cv;
                    *reinterpret_cast<float2*>(Cf + (size_t)row * ldc + col) = v0;
                    *reinterpret_cast<float2*>(Cf + (size_t)(row + 8) * ldc + col) = v1;
                }
            }
        }
    }
}

// ---------------------------------------------------------------------------
// Prep: fp32 -> fp16 bulk convert (8 elems/thread)
// ---------------------------------------------------------------------------
__global__ void f2h(const float4* __restrict__ in, __half2* __restrict__ out, int n8) {
    const int i = blockIdx.x * blockDim.x + threadIdx.x;
    if (i < n8) {
        float4 v0 = in[2 * i], v1 = in[2 * i + 1];
        out[4 * i]     = __floats2half2_rn(v0.x, v0.y);
        out[4 * i + 1] = __floats2half2_rn(v0.z, v0.w);
        out[4 * i + 2] = __floats2half2_rn(v1.x, v1.y);
        out[4 * i + 3] = __floats2half2_rn(v1.z, v1.w);
    }
}

// Weight prep: [K,N] fp32 row-major -> [N,K] fp16 row-major (dual via blockIdx.z)
__global__ void transpose_h(const float* __restrict__ in0, const float* __restrict__ in1,
                            __half* __restrict__ out0, __half* __restrict__ out1,
                            int K, int N) {
    __shared__ float t[32][33];
    const float* in  = blockIdx.z ? in1 : in0;
    __half*      out = blockIdx.z ? out1 : out0;
    const int n0 = blockIdx.x * 32, k0 = blockIdx.y * 32;
    const int tx = threadIdx.x, ty = threadIdx.y;   // 32 x 8
    #pragma unroll
    for (int j = 0; j < 32; j += 8)
        t[ty + j][tx] = in[(size_t)(k0 + ty + j) * N + n0 + tx];
    __syncthreads();
    #pragma unroll
    for (int j = 0; j < 32; j += 8)
        out[(size_t)(n0 + ty + j) * K + k0 + tx] = __float2half_rn(t[tx][ty + j]);
}

// ---------------------------------------------------------------------------
// GRU gate elementwise, 4 h per thread, fully vectorized loads/stores
// ---------------------------------------------------------------------------
__device__ __forceinline__ void load4h(const __half* p, float* o) {
    const __half2 v0 = *reinterpret_cast<const __half2*>(p);
    const __half2 v1 = *reinterpret_cast<const __half2*>(p + 2);
    const float2 f0 = __half22float2(v0), f1 = __half22float2(v1);
    o[0] = f0.x; o[1] = f0.y; o[2] = f1.x; o[3] = f1.y;
}
__device__ __forceinline__ float sigf(float x) {
    return 1.0f / (1.0f + __expf(-x));
}
__device__ __forceinline__ float tanhfast(float x) {
    // tanh(x) = 2*sigmoid(2x) - 1
    return 2.0f / (1.0f + __expf(-2.0f * x)) - 1.0f;
}

__global__ void gru_elem4(const __half* __restrict__ Rh, const float* __restrict__ prev_h,
                          const float* __restrict__ prev_y, const float* __restrict__ ccoarse,
                          const float* __restrict__ Icw, const float* __restrict__ Ifw,
                          const float* __restrict__ bu, const float* __restrict__ br,
                          const float* __restrict__ be,
                          float* __restrict__ hidden, __half* __restrict__ hA) {
    const int idx = blockIdx.x * blockDim.x + threadIdx.x;
    if (idx >= B_SZ * (H_SZ / 4)) return;
    const int b = idx / (H_SZ / 4);
    const int h = (idx - b * (H_SZ / 4)) * 4;

    const float2 py = *reinterpret_cast<const float2*>(prev_y + 2 * b);
    const float cc = ccoarse[b];

    // recurrent projections (fp16 -> fp32)
    const __half* r0 = Rh + (size_t)b * H3;
    float Ru[4], Rr[4], Re[4];
    load4h(r0 + h, Ru);
    load4h(r0 + H_SZ + h, Rr);
    load4h(r0 + 2 * H_SZ + h, Re);

    // input projections (vector weight loads; branch uniform since 448 % 4 == 0)
    float Iu[4], Ir[4], Ie[4];
    if (h < S_SZ) {
        const float4 wu0 = *reinterpret_cast<const float4*>(Icw + h);
        const float4 wu1 = *reinterpret_cast<const float4*>(Icw + S3 + h);
        const float4 wr0 = *reinterpret_cast<const float4*>(Icw + S_SZ + h);
        const float4 wr1 = *reinterpret_cast<const float4*>(Icw + S3 + S_SZ + h);
        const float4 we0 = *reinterpret_cast<const float4*>(Icw + 2 * S_SZ + h);
        const float4 we1 = *reinterpret_cast<const float4*>(Icw + S3 + 2 * S_SZ + h);
        const float* u0 = &wu0.x; const float* u1 = &wu1.x;
        const float* rr0 = &wr0.x; const float* rr1 = &wr1.x;
        const float* e0 = &we0.x; const float* e1 = &we1.x;
        #pragma unroll
        for (int j = 0; j < 4; ++j) {
            Iu[j] = py.x * u0[j] + py.y * u1[j];
            Ir[j] = py.x * rr0[j] + py.y * rr1[j];
            Ie[j] = py.x * e0[j] + py.y * e1[j];
        }
    } else {
        const int hh = h - S_SZ;
        const float4 wu0 = *reinterpret_cast<const float4*>(Ifw + hh);
        const float4 wu1 = *reinterpret_cast<const float4*>(Ifw + S3 + hh);
        const float4 wu2 = *reinterpret_cast<const float4*>(Ifw + 2 * S3 + hh);
        const float4 wr0 = *reinterpret_cast<const float4*>(Ifw + S_SZ + hh);
        const float4 wr1 = *reinterpret_cast<const float4*>(Ifw + S3 + S_SZ + hh);
        const float4 wr2 = *reinterpret_cast<const float4*>(Ifw + 2 * S3 + S_SZ + hh);
        const float4 we0 = *reinterpret_cast<const float4*>(Ifw + 2 * S_SZ + hh);
        const float4 we1 = *reinterpret_cast<const float4*>(Ifw + S3 + 2 * S_SZ + hh);
        const float4 we2 = *reinterpret_cast<const float4*>(Ifw + 2 * S3 + 2 * S_SZ + hh);
        const float* u0 = &wu0.x; const float* u1 = &wu1.x; const float* u2 = &wu2.x;
        const float* rr0 = &wr0.x; const float* rr1 = &wr1.x; const float* rr2 = &wr2.x;
        const float* e0 = &we0.x; const float* e1 = &we1.x; const float* e2 = &we2.x;
        #pragma unroll
        for (int j = 0; j < 4; ++j) {
            Iu[j] = py.x * u0[j] + py.y * u1[j] + cc * u2[j];
            Ir[j] = py.x * rr0[j] + py.y * rr1[j] + cc * rr2[j];
            Ie[j] = py.x * e0[j] + py.y * e1[j] + cc * e2[j];
        }
    }

    const float4 bu4 = *reinterpret_cast<const float4*>(bu + h);
    const float4 br4 = *reinterpret_cast<const float4*>(br + h);
    const float4 be4 = *reinterpret_cast<const float4*>(be + h);
    const float4 ph4 = *reinterpret_cast<const float4*>(prev_h + (size_t)b * H_SZ + h);
    const float* bup = &bu4.x; const float* brp = &br4.x; const float* bep = &be4.x;
    const float* php = &ph4.x;

    float hv[4];
    #pragma unroll
    for (int j = 0; j < 4; ++j) {
        const float u = sigf(Ru[j] + Iu[j] + bup[j]);
        const float r = sigf(Rr[j] + Ir[j] + brp[j]);
        const float e = tanhfast(r * Re[j] + Ie[j] + bep[j]);
        hv[j] = u * php[j] + (1.0f - u) * e;
    }

    *reinterpret_cast<float4*>(hidden + (size_t)b * H_SZ + h) =
        make_float4(hv[0], hv[1], hv[2], hv[3]);
    __half2* hap = reinterpret_cast<__half2*>(hA + (size_t)b * H_SZ + h);
    hap[0] = __floats2half2_rn(hv[0], hv[1]);
    hap[1] = __floats2half2_rn(hv[2], hv[3]);
}

// ---------------------------------------------------------------------------
// Launch
// ---------------------------------------------------------------------------
extern "C" void kernel_launch(void* const* d_in, const int* in_sizes, int n_in,
                              void* d_out, int out_size)
{
    const float* prev_y  = (const float*)d_in[0];
    const float* prev_h  = (const float*)d_in[1];
    const float* ccoarse = (const float*)d_in[2];
    const float* R_W     = (const float*)d_in[3];
    const float* Icw     = (const float*)d_in[4];
    const float* Ifw     = (const float*)d_in[5];
    const float* O1_W    = (const float*)d_in[6];
    const float* O1_b    = (const float*)d_in[7];
    const float* O2_W    = (const float*)d_in[8];
    const float* O2_b    = (const float*)d_in[9];
    const float* O3_W    = (const float*)d_in[10];
    const float* O3_b    = (const float*)d_in[11];
    const float* O4_W    = (const float*)d_in[12];
    const float* O4_b    = (const float*)d_in[13];
    const float* bu      = (const float*)d_in[14];
    const float* br      = (const float*)d_in[15];
    const float* be      = (const float*)d_in[16];

    float* out        = (float*)d_out;
    float* out_coarse = out;
    float* out_fine   = out + (size_t)B_SZ * Q_SZ;
    float* hidden     = out + (size_t)2 * B_SZ * Q_SZ;

    __half *Rh, *Ah, *hA, *hc, *hf, *RWt, *O1t, *O2t, *O3t, *O4t;
    cudaGetSymbolAddress((void**)&Rh,  g_Rh);
    cudaGetSymbolAddress((void**)&Ah,  g_Ah);
    cudaGetSymbolAddress((void**)&hA,  g_hA);
    cudaGetSymbolAddress((void**)&hc,  g_hc);
    cudaGetSymbolAddress((void**)&hf,  g_hf);
    cudaGetSymbolAddress((void**)&RWt, g_RWt);
    cudaGetSymbolAddress((void**)&O1t, g_O1t);
    cudaGetSymbolAddress((void**)&O2t, g_O2t);
    cudaGetSymbolAddress((void**)&O3t, g_O3t);
    cudaGetSymbolAddress((void**)&O4t, g_O4t);

    const int SMB = 4 * MATW * 4;   // 73728 bytes dynamic smem
    cudaFuncSetAttribute(hgemm<0, 1, 0>, cudaFuncAttributeMaxDynamicSharedMemorySize, SMB);
    cudaFuncSetAttribute(hgemm<1, 1, 1>, cudaFuncAttributeMaxDynamicSharedMemorySize, SMB);
    cudaFuncSetAttribute(hgemm<2, 0, 1>, cudaFuncAttributeMaxDynamicSharedMemorySize, SMB);

    // --- prep ---
    const int n8 = B_SZ * H_SZ / 8;
    f2h<<<(n8 + 255) / 256, 256>>>((const float4*)prev_h, (__half2*)Ah, n8);
    transpose_h<<<dim3(H3 / 32, H_SZ / 32, 1), dim3(32, 8)>>>(R_W, R_W, RWt, RWt, H_SZ, H3);
    transpose_h<<<dim3(S_SZ / 32, S_SZ / 32, 2), dim3(32, 8)>>>(O1_W, O3_W, O1t, O3t, S_SZ, S_SZ);
    transpose_h<<<dim3(Q_SZ / 32, S_SZ / 32, 2), dim3(32, 8)>>>(O2_W, O4_W, O2t, O4t, S_SZ, Q_SZ);

    const int MT = B_SZ / 128;   // 256 M-tiles

    // 1) Rh = Ah @ RWt^T   (fp16 in, fp16 out)
    hgemm<0, 1, 0><<<dim3(H3 / 128, MT, 1), 128, SMB>>>(
        Ah, nullptr, H_SZ, RWt, nullptr, H_SZ, nullptr, nullptr,
        Rh, nullptr, H3, H3, H_SZ);
    // 2) GRU gates -> hidden (fp32) + fp16 copy (vectorized 4/thread)
    gru_elem4<<<(B_SZ * (H_SZ / 4) + 255) / 256, 256>>>(
        Rh, prev_h, prev_y, ccoarse, Icw, Ifw, bu, br, be, hidden, hA);
    // 3+4) hc = relu(hidden_c @ O1 + b1); hf = relu(hidden_f @ O3 + b3)  [fp16 out]
    hgemm<1, 1, 1><<<dim3(4, MT, 2), 128, SMB>>>(
        hA, hA + S_SZ, H_SZ, O1t, O3t, S_SZ, O1_b, O3_b,
        hc, hf, S_SZ, S_SZ, S_SZ);
    // 5+6) out_coarse = hc @ O2 + b2; out_fine = hf @ O4 + b4  [fp32 out]
    hgemm<2, 0, 1><<<dim3(2, MT, 2), 128, SMB>>>(
        hc, hf, S_SZ, O2t, O4t, S_SZ, O2_b, O4_b,
        out_coarse, out_fine, Q_SZ, Q_SZ, S_SZ);
}

// round 13
// speedup vs baseline: 1.2820x; 1.0062x over previous
#include <cuda_runtime.h>
#include <cuda_fp16.h>
#include <math.h>
#include <stdint.h>

// Problem dims (fixed)
#define B_SZ 32768
#define H_SZ 896
#define S_SZ 448
#define Q_SZ 256
#define H3   2688
#define S3   1344

// ---------------------------------------------------------------------------
// Scratch (device globals; allocation-free per harness rules)
// ---------------------------------------------------------------------------
__device__ __half g_Rh [(size_t)B_SZ * H3];      // R_hidden fp16
__device__ __half g_Ah [(size_t)B_SZ * H_SZ];    // fp16 prev_hidden
__device__ __half g_hA [(size_t)B_SZ * H_SZ];    // fp16 hidden
__device__ __half g_hc [(size_t)B_SZ * S_SZ];
__device__ __half g_hf [(size_t)B_SZ * S_SZ];
__device__ __half g_RWt[(size_t)H3 * H_SZ];
__device__ __half g_O1t[S_SZ * S_SZ];
__device__ __half g_O2t[Q_SZ * S_SZ];
__device__ __half g_O3t[S_SZ * S_SZ];
__device__ __half g_O4t[Q_SZ * S_SZ];

// ---------------------------------------------------------------------------
// Helpers (non-arch-specific PTX only: must assemble for plain sm_103)
// ---------------------------------------------------------------------------
__device__ __forceinline__ uint32_t smem_u32(const void* p) {
    uint32_t a;
    asm("{ .reg .u64 t; cvta.to.shared.u64 t, %1; cvt.u32.u64 %0, t; }" : "=r"(a) : "l"(p));
    return a;
}
__device__ __forceinline__ void cp_async16(uint32_t s, const void* g) {
    asm volatile("cp.async.cg.shared.global [%0], [%1], 16;\n" :: "r"(s), "l"(g));
}
#define CP_COMMIT()  asm volatile("cp.async.commit_group;\n" ::)
#define CP_WAIT(n)   asm volatile("cp.async.wait_group %0;\n" :: "n"(n))

__device__ __forceinline__ void mma_16816(float* d, const uint32_t* a, const uint32_t* b) {
    asm volatile(
        "mma.sync.aligned.m16n8k16.row.col.f32.f16.f16.f32 "
        "{%0,%1,%2,%3}, {%4,%5,%6,%7}, {%8,%9}, {%0,%1,%2,%3};"
        : "+f"(d[0]), "+f"(d[1]), "+f"(d[2]), "+f"(d[3])
        : "r"(a[0]), "r"(a[1]), "r"(a[2]), "r"(a[3]), "r"(b[0]), "r"(b[1]));
}

// ---------------------------------------------------------------------------
// fp16 mma.sync GEMM: C[M,N] = A[M,K] @ Bt[N,K]^T (+bias)(+relu)
// CTA tile 128 x BN (BN divides N exactly -> NO guards), BK=64 fp16.
// 128 thr = 4 warps (2x2), warp tile 64 x (BN/2).
// EPI: 0=none, 1=bias+relu, 2=bias.  HOUT: 1 = __half C, 0 = float C.
// DUAL: blockIdx.z selects problem set.
// ---------------------------------------------------------------------------
#define PW 36                     // words (4B) per smem row: 64 halves + 16B pad

template <int BN, int EPI, int HOUT, int DUAL>
__global__ void __launch_bounds__(128, 2)
hgemm(const __half* __restrict__ A0, const __half* __restrict__ A1, int lda,
      const __half* __restrict__ B0, const __half* __restrict__ B1, int ldb,
      const float* __restrict__ bias0, const float* __restrict__ bias1,
      void* __restrict__ C0v, void* __restrict__ C1v, int ldc, int K)
{
    constexpr int AW   = 128 * PW;        // A words per buffer
    constexpr int BW   = BN * PW;         // B words per buffer
    constexpr int BUFW = AW + BW;
    constexpr int NF   = BN / 16;         // B n-fragments per warp
    constexpr int WN   = BN / 2;          // warp tile N

    extern __shared__ uint32_t smw[];
    const __half* A    = (DUAL && blockIdx.z) ? A1 : A0;
    const __half* Bt   = (DUAL && blockIdx.z) ? B1 : B0;
    const float*  bias = (DUAL && blockIdx.z) ? bias1 : bias0;
    void*         Cv   = (DUAL && blockIdx.z) ? C1v : C0v;

    const int tid = threadIdx.x;
    const int lane = tid & 31, w = tid >> 5;
    const int wr = w >> 1, wc = w & 1;        // 2x2 warps
    const int lq = lane >> 2, ln = lane & 3;

    const int rowBase = blockIdx.y * 128;
    const int colBase = blockIdx.x * BN;

    const uint32_t sBase = smem_u32(smw);
    const int r0 = tid >> 3, c16 = tid & 7;           // row 0..15, 16B-col 0..7
    const uint32_t dstOff = (uint32_t)((r0 * PW + c16 * 4) * 4);
    const __half* Abase = A + (size_t)(rowBase + r0) * lda + c16 * 8;
    const __half* Bbase = Bt + (size_t)(colBase + r0) * ldb + c16 * 8;

    auto load_tile = [&](int buf, int it) {
        const int kb = it * 64;
        const uint32_t base = sBase + (uint32_t)(buf * BUFW * 4);
        #pragma unroll
        for (int i = 0; i < 8; ++i)
            cp_async16(base + dstOff + (uint32_t)(i * 16 * PW * 4),
                       Abase + kb + (size_t)(i * 16) * lda);
        #pragma unroll
        for (int i = 0; i < BN / 16; ++i)
            cp_async16(base + (uint32_t)(AW * 4) + dstOff + (uint32_t)(i * 16 * PW * 4),
                       Bbase + kb + (size_t)(i * 16) * ldb);
        CP_COMMIT();
    };

    float acc[4][NF][4];
    #pragma unroll
    for (int i = 0; i < 4; ++i)
        #pragma unroll
        for (int j = 0; j < NF; ++j)
            #pragma unroll
            for (int k = 0; k < 4; ++k) acc[i][j][k] = 0.0f;

    const int nit = K >> 6;
    load_tile(0, 0);

    for (int it = 0; it < nit; ++it) {
        const int buf = it & 1;
        if (it + 1 < nit) { load_tile(buf ^ 1, it + 1); CP_WAIT(1); }
        else              { CP_WAIT(0); }
        __syncthreads();

        const uint32_t* Ab = smw + buf * BUFW;
        const uint32_t* Bb = Ab + AW;

        #pragma unroll
        for (int s = 0; s < 4; ++s) {          // 4 x K=16 steps
            const int k8 = s * 8;
            uint32_t a[4][4], b[NF][2];
            #pragma unroll
            for (int mf = 0; mf < 4; ++mf) {
                const int m = wr * 64 + mf * 16 + lq;
                a[mf][0] = Ab[m * PW + k8 + ln];
                a[mf][1] = Ab[(m + 8) * PW + k8 + ln];
                a[mf][2] = Ab[m * PW + k8 + ln + 4];
                a[mf][3] = Ab[(m + 8) * PW + k8 + ln + 4];
            }
            #pragma unroll
            for (int nf = 0; nf < NF; ++nf) {
                const int n = wc * WN + nf * 8 + lq;
                b[nf][0] = Bb[n * PW + k8 + ln];
                b[nf][1] = Bb[n * PW + k8 + ln + 4];
            }
            #pragma unroll
            for (int mf = 0; mf < 4; ++mf)
                #pragma unroll
                for (int nf = 0; nf < NF; ++nf)
                    mma_16816(acc[mf][nf], a[mf], b[nf]);
        }
        __syncthreads();
    }

    // ---- epilogue (no N guards: exact tiling) ----
    #pragma unroll
    for (int nf = 0; nf < NF; ++nf) {
        const int col = colBase + wc * WN + nf * 8 + ln * 2;
        float2 bv = make_float2(0.0f, 0.0f);
        if (EPI) bv = *reinterpret_cast<const float2*>(bias + col);
        #pragma unroll
        for (int mf = 0; mf < 4; ++mf) {
            const int row = rowBase + wr * 64 + mf * 16 + lq;
            float2 v0 = make_float2(acc[mf][nf][0], acc[mf][nf][1]);
            float2 v1 = make_float2(acc[mf][nf][2], acc[mf][nf][3]);
            if (EPI) {
                v0.x += bv.x; v0.y += bv.y; v1.x += bv.x; v1.y += bv.y;
                if (EPI == 1) {
                    v0.x = fmaxf(v0.x, 0.0f); v0.y = fmaxf(v0.y, 0.0f);
                    v1.x = fmaxf(v1.x, 0.0f); v1.y = fmaxf(v1.y, 0.0f);
                }
            }
            if (HOUT) {
                __half* Ch = (__half*)Cv;
                *reinterpret_cast<__half2*>(Ch + (size_t)row * ldc + col) =
                    __floats2half2_rn(v0.x, v0.y);
                *reinterpret_cast<__half2*>(Ch + (size_t)(row + 8) * ldc + col) =
                    __floats2half2_rn(v1.x, v1.y);
            } else {
                float* Cf = (float*)Cv;
                *reinterpret_cast<float2*>(Cf + (size_t)row * ldc + col) = v0;
                *reinterpret_cast<float2*>(Cf + (size_t)(row + 8) * ldc + col) = v1;
            }
        }
    }
}

// ---------------------------------------------------------------------------
// Prep: fp32 -> fp16 bulk convert (8 elems/thread)
// ---------------------------------------------------------------------------
__global__ void f2h(const float4* __restrict__ in, __half2* __restrict__ out, int n8) {
    const int i = blockIdx.x * blockDim.x + threadIdx.x;
    if (i < n8) {
        float4 v0 = in[2 * i], v1 = in[2 * i + 1];
        out[4 * i]     = __floats2half2_rn(v0.x, v0.y);
        out[4 * i + 1] = __floats2half2_rn(v0.z, v0.w);
        out[4 * i + 2] = __floats2half2_rn(v1.x, v1.y);
        out[4 * i + 3] = __floats2half2_rn(v1.z, v1.w);
    }
}

// Weight prep: [K,N] fp32 row-major -> [N,K] fp16 row-major (dual via blockIdx.z)
__global__ void transpose_h(const float* __restrict__ in0, const float* __restrict__ in1,
                            __half* __restrict__ out0, __half* __restrict__ out1,
                            int K, int N) {
    __shared__ float t[32][33];
    const float* in  = blockIdx.z ? in1 : in0;
    __half*      out = blockIdx.z ? out1 : out0;
    const int n0 = blockIdx.x * 32, k0 = blockIdx.y * 32;
    const int tx = threadIdx.x, ty = threadIdx.y;   // 32 x 8
    #pragma unroll
    for (int j = 0; j < 32; j += 8)
        t[ty + j][tx] = in[(size_t)(k0 + ty + j) * N + n0 + tx];
    __syncthreads();
    #pragma unroll
    for (int j = 0; j < 32; j += 8)
        out[(size_t)(n0 + ty + j) * K + k0 + tx] = __float2half_rn(t[tx][ty + j]);
}

// ---------------------------------------------------------------------------
// GRU gate elementwise, 4 h per thread, fully vectorized loads/stores
// ---------------------------------------------------------------------------
__device__ __forceinline__ void load4h(const __half* p, float* o) {
    const __half2 v0 = *reinterpret_cast<const __half2*>(p);
    const __half2 v1 = *reinterpret_cast<const __half2*>(p + 2);
    const float2 f0 = __half22float2(v0), f1 = __half22float2(v1);
    o[0] = f0.x; o[1] = f0.y; o[2] = f1.x; o[3] = f1.y;
}
__device__ __forceinline__ float sigf(float x) {
    return 1.0f / (1.0f + __expf(-x));
}
__device__ __forceinline__ float tanhfast(float x) {
    return 2.0f / (1.0f + __expf(-2.0f * x)) - 1.0f;
}

__global__ void gru_elem4(const __half* __restrict__ Rh, const float* __restrict__ prev_h,
                          const float* __restrict__ prev_y, const float* __restrict__ ccoarse,
                          const float* __restrict__ Icw, const float* __restrict__ Ifw,
                          const float* __restrict__ bu, const float* __restrict__ br,
                          const float* __restrict__ be,
                          float* __restrict__ hidden, __half* __restrict__ hA) {
    const int idx = blockIdx.x * blockDim.x + threadIdx.x;
    if (idx >= B_SZ * (H_SZ / 4)) return;
    const int b = idx / (H_SZ / 4);
    const int h = (idx - b * (H_SZ / 4)) * 4;

    const float2 py = *reinterpret_cast<const float2*>(prev_y + 2 * b);
    const float cc = ccoarse[b];

    const __half* r0 = Rh + (size_t)b * H3;
    float Ru[4], Rr[4], Re[4];
    load4h(r0 + h, Ru);
    load4h(r0 + H_SZ + h, Rr);
    load4h(r0 + 2 * H_SZ + h, Re);

    float Iu[4], Ir[4], Ie[4];
    if (h < S_SZ) {
        const float4 wu0 = *reinterpret_cast<const float4*>(Icw + h);
        const float4 wu1 = *reinterpret_cast<const float4*>(Icw + S3 + h);
        const float4 wr0 = *reinterpret_cast<const float4*>(Icw + S_SZ + h);
        const float4 wr1 = *reinterpret_cast<const float4*>(Icw + S3 + S_SZ + h);
        const float4 we0 = *reinterpret_cast<const float4*>(Icw + 2 * S_SZ + h);
        const float4 we1 = *reinterpret_cast<const float4*>(Icw + S3 + 2 * S_SZ + h);
        const float* u0 = &wu0.x; const float* u1 = &wu1.x;
        const float* rr0 = &wr0.x; const float* rr1 = &wr1.x;
        const float* e0 = &we0.x; const float* e1 = &we1.x;
        #pragma unroll
        for (int j = 0; j < 4; ++j) {
            Iu[j] = py.x * u0[j] + py.y * u1[j];
            Ir[j] = py.x * rr0[j] + py.y * rr1[j];
            Ie[j] = py.x * e0[j] + py.y * e1[j];
        }
    } else {
        const int hh = h - S_SZ;
        const float4 wu0 = *reinterpret_cast<const float4*>(Ifw + hh);
        const float4 wu1 = *reinterpret_cast<const float4*>(Ifw + S3 + hh);
        const float4 wu2 = *reinterpret_cast<const float4*>(Ifw + 2 * S3 + hh);
        const float4 wr0 = *reinterpret_cast<const float4*>(Ifw + S_SZ + hh);
        const float4 wr1 = *reinterpret_cast<const float4*>(Ifw + S3 + S_SZ + hh);
        const float4 wr2 = *reinterpret_cast<const float4*>(Ifw + 2 * S3 + S_SZ + hh);
        const float4 we0 = *reinterpret_cast<const float4*>(Ifw + 2 * S_SZ + hh);
        const float4 we1 = *reinterpret_cast<const float4*>(Ifw + S3 + 2 * S_SZ + hh);
        const float4 we2 = *reinterpret_cast<const float4*>(Ifw + 2 * S3 + 2 * S_SZ + hh);
        const float* u0 = &wu0.x; const float* u1 = &wu1.x; const float* u2 = &wu2.x;
        const float* rr0 = &wr0.x; const float* rr1 = &wr1.x; const float* rr2 = &wr2.x;
        const float* e0 = &we0.x; const float* e1 = &we1.x; const float* e2 = &we2.x;
        #pragma unroll
        for (int j = 0; j < 4; ++j) {
            Iu[j] = py.x * u0[j] + py.y * u1[j] + cc * u2[j];
            Ir[j] = py.x * rr0[j] + py.y * rr1[j] + cc * rr2[j];
            Ie[j] = py.x * e0[j] + py.y * e1[j] + cc * e2[j];
        }
    }

    const float4 bu4 = *reinterpret_cast<const float4*>(bu + h);
    const float4 br4 = *reinterpret_cast<const float4*>(br + h);
    const float4 be4 = *reinterpret_cast<const float4*>(be + h);
    const float4 ph4 = *reinterpret_cast<const float4*>(prev_h + (size_t)b * H_SZ + h);
    const float* bup = &bu4.x; const float* brp = &br4.x; const float* bep = &be4.x;
    const float* php = &ph4.x;

    float hv[4];
    #pragma unroll
    for (int j = 0; j < 4; ++j) {
        const float u = sigf(Ru[j] + Iu[j] + bup[j]);
        const float r = sigf(Rr[j] + Ir[j] + brp[j]);
        const float e = tanhfast(r * Re[j] + Ie[j] + bep[j]);
        hv[j] = u * php[j] + (1.0f - u) * e;
    }

    *reinterpret_cast<float4*>(hidden + (size_t)b * H_SZ + h) =
        make_float4(hv[0], hv[1], hv[2], hv[3]);
    __half2* hap = reinterpret_cast<__half2*>(hA + (size_t)b * H_SZ + h);
    hap[0] = __floats2half2_rn(hv[0], hv[1]);
    hap[1] = __floats2half2_rn(hv[2], hv[3]);
}

// ---------------------------------------------------------------------------
// Launch
// ---------------------------------------------------------------------------
extern "C" void kernel_launch(void* const* d_in, const int* in_sizes, int n_in,
                              void* d_out, int out_size)
{
    const float* prev_y  = (const float*)d_in[0];
    const float* prev_h  = (const float*)d_in[1];
    const float* ccoarse = (const float*)d_in[2];
    const float* R_W     = (const float*)d_in[3];
    const float* Icw     = (const float*)d_in[4];
    const float* Ifw     = (const float*)d_in[5];
    const float* O1_W    = (const float*)d_in[6];
    const float* O1_b    = (const float*)d_in[7];
    const float* O2_W    = (const float*)d_in[8];
    const float* O2_b    = (const float*)d_in[9];
    const float* O3_W    = (const float*)d_in[10];
    const float* O3_b    = (const float*)d_in[11];
    const float* O4_W    = (const float*)d_in[12];
    const float* O4_b    = (const float*)d_in[13];
    const float* bu      = (const float*)d_in[14];
    const float* br      = (const float*)d_in[15];
    const float* be      = (const float*)d_in[16];

    float* out        = (float*)d_out;
    float* out_coarse = out;
    float* out_fine   = out + (size_t)B_SZ * Q_SZ;
    float* hidden     = out + (size_t)2 * B_SZ * Q_SZ;

    __half *Rh, *Ah, *hA, *hc, *hf, *RWt, *O1t, *O2t, *O3t, *O4t;
    cudaGetSymbolAddress((void**)&Rh,  g_Rh);
    cudaGetSymbolAddress((void**)&Ah,  g_Ah);
    cudaGetSymbolAddress((void**)&hA,  g_hA);
    cudaGetSymbolAddress((void**)&hc,  g_hc);
    cudaGetSymbolAddress((void**)&hf,  g_hf);
    cudaGetSymbolAddress((void**)&RWt, g_RWt);
    cudaGetSymbolAddress((void**)&O1t, g_O1t);
    cudaGetSymbolAddress((void**)&O2t, g_O2t);
    cudaGetSymbolAddress((void**)&O3t, g_O3t);
    cudaGetSymbolAddress((void**)&O4t, g_O4t);

    const int SMB128 = 2 * (128 + 128) * PW * 4;   // 73728
    const int SMB112 = 2 * (128 + 112) * PW * 4;   // 69120
    cudaFuncSetAttribute(hgemm<128, 0, 1, 0>, cudaFuncAttributeMaxDynamicSharedMemorySize, SMB128);
    cudaFuncSetAttribute(hgemm<112, 1, 1, 1>, cudaFuncAttributeMaxDynamicSharedMemorySize, SMB112);
    cudaFuncSetAttribute(hgemm<128, 2, 0, 1>, cudaFuncAttributeMaxDynamicSharedMemorySize, SMB128);

    // --- prep ---
    const int n8 = B_SZ * H_SZ / 8;
    f2h<<<(n8 + 255) / 256, 256>>>((const float4*)prev_h, (__half2*)Ah, n8);
    transpose_h<<<dim3(H3 / 32, H_SZ / 32, 1), dim3(32, 8)>>>(R_W, R_W, RWt, RWt, H_SZ, H3);
    transpose_h<<<dim3(S_SZ / 32, S_SZ / 32, 2), dim3(32, 8)>>>(O1_W, O3_W, O1t, O3t, S_SZ, S_SZ);
    transpose_h<<<dim3(Q_SZ / 32, S_SZ / 32, 2), dim3(32, 8)>>>(O2_W, O4_W, O2t, O4t, S_SZ, Q_SZ);

    const int MT = B_SZ / 128;   // 256 M-tiles

    // 1) Rh = Ah @ RWt^T   (fp16 in, fp16 out)  N=2688=21x128 exact
    hgemm<128, 0, 1, 0><<<dim3(H3 / 128, MT, 1), 128, SMB128>>>(
        Ah, nullptr, H_SZ, RWt, nullptr, H_SZ, nullptr, nullptr,
        Rh, nullptr, H3, H_SZ);
    // 2) GRU gates -> hidden (fp32) + fp16 copy (vectorized 4/thread)
    gru_elem4<<<(B_SZ * (H_SZ / 4) + 255) / 256, 256>>>(
        Rh, prev_h, prev_y, ccoarse, Icw, Ifw, bu, br, be, hidden, hA);
    // 3+4) heads layer 1: N=448=4x112 exact (BN=112)
    hgemm<112, 1, 1, 1><<<dim3(S_SZ / 112, MT, 2), 128, SMB112>>>(
        hA, hA + S_SZ, H_SZ, O1t, O3t, S_SZ, O1_b, O3_b,
        hc, hf, S_SZ, S_SZ);
    // 5+6) heads layer 2: N=256=2x128 exact
    hgemm<128, 2, 0, 1><<<dim3(Q_SZ / 128, MT, 2), 128, SMB128>>>(
        hc, hf, S_SZ, O2t, O4t, S_SZ, O2_b, O4_b,
        out_coarse, out_fine, Q_SZ, S_SZ);
}

// round 14
// speedup vs baseline: 1.2906x; 1.0067x over previous
#include <cuda_runtime.h>
#include <cuda_fp16.h>
#include <math.h>
#include <stdint.h>

// Problem dims (fixed)
#define B_SZ 32768
#define H_SZ 896
#define S_SZ 448
#define Q_SZ 256
#define H3   2688
#define S3   1344

// ---------------------------------------------------------------------------
// Scratch (device globals; allocation-free per harness rules)
// ---------------------------------------------------------------------------
__device__ __half g_Rh [(size_t)B_SZ * H3];      // R_hidden fp16
__device__ __half g_Ah [(size_t)B_SZ * H_SZ];    // fp16 prev_hidden
__device__ __half g_hA [(size_t)B_SZ * H_SZ];    // fp16 hidden
__device__ __half g_hc [(size_t)B_SZ * S_SZ];
__device__ __half g_hf [(size_t)B_SZ * S_SZ];
__device__ __half g_RWt[(size_t)H3 * H_SZ];
__device__ __half g_O1t[S_SZ * S_SZ];
__device__ __half g_O2t[Q_SZ * S_SZ];
__device__ __half g_O3t[S_SZ * S_SZ];
__device__ __half g_O4t[Q_SZ * S_SZ];

// ---------------------------------------------------------------------------
// Helpers (non-arch-specific PTX only: must assemble for plain sm_103)
// ---------------------------------------------------------------------------
__device__ __forceinline__ uint32_t smem_u32(const void* p) {
    uint32_t a;
    asm("{ .reg .u64 t; cvta.to.shared.u64 t, %1; cvt.u32.u64 %0, t; }" : "=r"(a) : "l"(p));
    return a;
}
__device__ __forceinline__ void cp_async16(uint32_t s, const void* g) {
    asm volatile("cp.async.cg.shared.global [%0], [%1], 16;\n" :: "r"(s), "l"(g));
}
#define CP_COMMIT()  asm volatile("cp.async.commit_group;\n" ::)
#define CP_WAIT(n)   asm volatile("cp.async.wait_group %0;\n" :: "n"(n))

__device__ __forceinline__ void mma_16816(float* d, const uint32_t* a, const uint32_t* b) {
    asm volatile(
        "mma.sync.aligned.m16n8k16.row.col.f32.f16.f16.f32 "
        "{%0,%1,%2,%3}, {%4,%5,%6,%7}, {%8,%9}, {%0,%1,%2,%3};"
        : "+f"(d[0]), "+f"(d[1]), "+f"(d[2]), "+f"(d[3])
        : "r"(a[0]), "r"(a[1]), "r"(a[2]), "r"(a[3]), "r"(b[0]), "r"(b[1]));
}

// ---------------------------------------------------------------------------
// fp16 mma.sync GEMM: C[M,N] = A[M,K] @ Bt[N,K]^T (+bias)(+relu)
// CTA tile 128 x BN (BN divides N exactly -> NO guards), BK=64 fp16.
// 128 thr = 4 warps (2x2), warp tile 64 x (BN/2).
// EPI: 0=none, 1=bias+relu, 2=bias.  HOUT: 1 = __half C, 0 = float C.
// DUAL: blockIdx.z selects problem set.
// ---------------------------------------------------------------------------
#define PW 36                     // words (4B) per smem row: 64 halves + 16B pad

template <int BN, int EPI, int HOUT, int DUAL>
__global__ void __launch_bounds__(128, 2)
hgemm(const __half* __restrict__ A0, const __half* __restrict__ A1, int lda,
      const __half* __restrict__ B0, const __half* __restrict__ B1, int ldb,
      const float* __restrict__ bias0, const float* __restrict__ bias1,
      void* __restrict__ C0v, void* __restrict__ C1v, int ldc, int K)
{
    constexpr int AW   = 128 * PW;
    constexpr int BW   = BN * PW;
    constexpr int BUFW = AW + BW;
    constexpr int NF   = BN / 16;
    constexpr int WN   = BN / 2;

    extern __shared__ uint32_t smw[];
    const __half* A    = (DUAL && blockIdx.z) ? A1 : A0;
    const __half* Bt   = (DUAL && blockIdx.z) ? B1 : B0;
    const float*  bias = (DUAL && blockIdx.z) ? bias1 : bias0;
    void*         Cv   = (DUAL && blockIdx.z) ? C1v : C0v;

    const int tid = threadIdx.x;
    const int lane = tid & 31, w = tid >> 5;
    const int wr = w >> 1, wc = w & 1;
    const int lq = lane >> 2, ln = lane & 3;

    const int rowBase = blockIdx.y * 128;
    const int colBase = blockIdx.x * BN;

    const uint32_t sBase = smem_u32(smw);
    const int r0 = tid >> 3, c16 = tid & 7;
    const uint32_t dstOff = (uint32_t)((r0 * PW + c16 * 4) * 4);
    const __half* Abase = A + (size_t)(rowBase + r0) * lda + c16 * 8;
    const __half* Bbase = Bt + (size_t)(colBase + r0) * ldb + c16 * 8;

    auto load_tile = [&](int buf, int it) {
        const int kb = it * 64;
        const uint32_t base = sBase + (uint32_t)(buf * BUFW * 4);
        #pragma unroll
        for (int i = 0; i < 8; ++i)
            cp_async16(base + dstOff + (uint32_t)(i * 16 * PW * 4),
                       Abase + kb + (size_t)(i * 16) * lda);
        #pragma unroll
        for (int i = 0; i < BN / 16; ++i)
            cp_async16(base + (uint32_t)(AW * 4) + dstOff + (uint32_t)(i * 16 * PW * 4),
                       Bbase + kb + (size_t)(i * 16) * ldb);
        CP_COMMIT();
    };

    float acc[4][NF][4];
    #pragma unroll
    for (int i = 0; i < 4; ++i)
        #pragma unroll
        for (int j = 0; j < NF; ++j)
            #pragma unroll
            for (int k = 0; k < 4; ++k) acc[i][j][k] = 0.0f;

    const int nit = K >> 6;
    load_tile(0, 0);

    for (int it = 0; it < nit; ++it) {
        const int buf = it & 1;
        if (it + 1 < nit) { load_tile(buf ^ 1, it + 1); CP_WAIT(1); }
        else              { CP_WAIT(0); }
        __syncthreads();

        const uint32_t* Ab = smw + buf * BUFW;
        const uint32_t* Bb = Ab + AW;

        #pragma unroll
        for (int s = 0; s < 4; ++s) {
            const int k8 = s * 8;
            uint32_t a[4][4], b[NF][2];
            #pragma unroll
            for (int mf = 0; mf < 4; ++mf) {
                const int m = wr * 64 + mf * 16 + lq;
                a[mf][0] = Ab[m * PW + k8 + ln];
                a[mf][1] = Ab[(m + 8) * PW + k8 + ln];
                a[mf][2] = Ab[m * PW + k8 + ln + 4];
                a[mf][3] = Ab[(m + 8) * PW + k8 + ln + 4];
            }
            #pragma unroll
            for (int nf = 0; nf < NF; ++nf) {
                const int n = wc * WN + nf * 8 + lq;
                b[nf][0] = Bb[n * PW + k8 + ln];
                b[nf][1] = Bb[n * PW + k8 + ln + 4];
            }
            #pragma unroll
            for (int mf = 0; mf < 4; ++mf)
                #pragma unroll
                for (int nf = 0; nf < NF; ++nf)
                    mma_16816(acc[mf][nf], a[mf], b[nf]);
        }
        __syncthreads();
    }

    #pragma unroll
    for (int nf = 0; nf < NF; ++nf) {
        const int col = colBase + wc * WN + nf * 8 + ln * 2;
        float2 bv = make_float2(0.0f, 0.0f);
        if (EPI) bv = *reinterpret_cast<const float2*>(bias + col);
        #pragma unroll
        for (int mf = 0; mf < 4; ++mf) {
            const int row = rowBase + wr * 64 + mf * 16 + lq;
            float2 v0 = make_float2(acc[mf][nf][0], acc[mf][nf][1]);
            float2 v1 = make_float2(acc[mf][nf][2], acc[mf][nf][3]);
            if (EPI) {
                v0.x += bv.x; v0.y += bv.y; v1.x += bv.x; v1.y += bv.y;
                if (EPI == 1) {
                    v0.x = fmaxf(v0.x, 0.0f); v0.y = fmaxf(v0.y, 0.0f);
                    v1.x = fmaxf(v1.x, 0.0f); v1.y = fmaxf(v1.y, 0.0f);
                }
            }
            if (HOUT) {
                __half* Ch = (__half*)Cv;
                *reinterpret_cast<__half2*>(Ch + (size_t)row * ldc + col) =
                    __floats2half2_rn(v0.x, v0.y);
                *reinterpret_cast<__half2*>(Ch + (size_t)(row + 8) * ldc + col) =
                    __floats2half2_rn(v1.x, v1.y);
            } else {
                float* Cf = (float*)Cv;
                *reinterpret_cast<float2*>(Cf + (size_t)row * ldc + col) = v0;
                *reinterpret_cast<float2*>(Cf + (size_t)(row + 8) * ldc + col) = v1;
            }
        }
    }
}

// ---------------------------------------------------------------------------
// Mega-prep: ONE launch. Block-range dispatch:
//   [0, NB_F2H)              : prev_h fp32 -> Ah fp16 (8 elems/thread)
//   [NB_F2H, +NB_RW)         : R_W transpose  (896 x 2688)
//   [.., +NB_O13)            : O1/O3 transpose (448 x 448), z via range
//   [.., +NB_O24)            : O2/O4 transpose (448 x 256)
// ---------------------------------------------------------------------------
#define NB_F2H  (B_SZ * H_SZ / 8 / 256)            // 14336
#define NB_RW   ((H3 / 32) * (H_SZ / 32))          // 84*28 = 2352
#define NB_O13  (2 * (S_SZ / 32) * (S_SZ / 32))    // 2*14*14 = 392
#define NB_O24  (2 * (Q_SZ / 32) * (S_SZ / 32))    // 2*8*14 = 224
#define NB_PREP (NB_F2H + NB_RW + NB_O13 + NB_O24)

__device__ __forceinline__ void transpose_body(
    const float* __restrict__ in, __half* __restrict__ out,
    int K, int N, int bx, int by, int tid, float (*t)[33])
{
    const int n0 = bx * 32, k0 = by * 32;
    const int tx = tid & 31, ty = tid >> 5;   // 32 x 8
    #pragma unroll
    for (int j = 0; j < 32; j += 8)
        t[ty + j][tx] = in[(size_t)(k0 + ty + j) * N + n0 + tx];
    __syncthreads();
    #pragma unroll
    for (int j = 0; j < 32; j += 8)
        out[(size_t)(n0 + ty + j) * K + k0 + tx] = __float2half_rn(t[tx][ty + j]);
}

__global__ void __launch_bounds__(256)
prep_all(const float* __restrict__ prev_h, __half* __restrict__ Ah,
         const float* __restrict__ R_W,  __half* __restrict__ RWt,
         const float* __restrict__ O1_W, __half* __restrict__ O1t,
         const float* __restrict__ O3_W, __half* __restrict__ O3t,
         const float* __restrict__ O2_W, __half* __restrict__ O2t,
         const float* __restrict__ O4_W, __half* __restrict__ O4t)
{
    __shared__ float t[32][33];
    const int tid = threadIdx.x;
    int b = blockIdx.x;

    if (b < NB_F2H) {
        const int i = b * 256 + tid;
        const float4* in = (const float4*)prev_h;
        __half2* out = (__half2*)Ah;
        float4 v0 = in[2 * i], v1 = in[2 * i + 1];
        out[4 * i]     = __floats2half2_rn(v0.x, v0.y);
        out[4 * i + 1] = __floats2half2_rn(v0.z, v0.w);
        out[4 * i + 2] = __floats2half2_rn(v1.x, v1.y);
        out[4 * i + 3] = __floats2half2_rn(v1.z, v1.w);
        return;
    }
    b -= NB_F2H;
    if (b < NB_RW) {
        transpose_body(R_W, RWt, H_SZ, H3, b % (H3 / 32), b / (H3 / 32), tid, t);
        return;
    }
    b -= NB_RW;
    if (b < NB_O13) {
        const int half = NB_O13 / 2;
        const float* in  = (b < half) ? O1_W : O3_W;
        __half*      out = (b < half) ? O1t  : O3t;
        const int bb = (b < half) ? b : b - half;
        transpose_body(in, out, S_SZ, S_SZ, bb % (S_SZ / 32), bb / (S_SZ / 32), tid, t);
        return;
    }
    b -= NB_O13;
    {
        const int half = NB_O24 / 2;
        const float* in  = (b < half) ? O2_W : O4_W;
        __half*      out = (b < half) ? O2t  : O4t;
        const int bb = (b < half) ? b : b - half;
        transpose_body(in, out, S_SZ, Q_SZ, bb % (Q_SZ / 32), bb / (Q_SZ / 32), tid, t);
    }
}

// ---------------------------------------------------------------------------
// GRU gate elementwise, 4 h per thread; prev_h read as fp16 (Ah)
// ---------------------------------------------------------------------------
__device__ __forceinline__ void load4h(const __half* p, float* o) {
    const __half2 v0 = *reinterpret_cast<const __half2*>(p);
    const __half2 v1 = *reinterpret_cast<const __half2*>(p + 2);
    const float2 f0 = __half22float2(v0), f1 = __half22float2(v1);
    o[0] = f0.x; o[1] = f0.y; o[2] = f1.x; o[3] = f1.y;
}
__device__ __forceinline__ float sigf(float x) {
    return 1.0f / (1.0f + __expf(-x));
}
__device__ __forceinline__ float tanhfast(float x) {
    return 2.0f / (1.0f + __expf(-2.0f * x)) - 1.0f;
}

__global__ void gru_elem4(const __half* __restrict__ Rh, const __half* __restrict__ Ah,
                          const float* __restrict__ prev_y, const float* __restrict__ ccoarse,
                          const float* __restrict__ Icw, const float* __restrict__ Ifw,
                          const float* __restrict__ bu, const float* __restrict__ br,
                          const float* __restrict__ be,
                          float* __restrict__ hidden, __half* __restrict__ hA) {
    const int idx = blockIdx.x * blockDim.x + threadIdx.x;
    if (idx >= B_SZ * (H_SZ / 4)) return;
    const int b = idx / (H_SZ / 4);
    const int h = (idx - b * (H_SZ / 4)) * 4;

    const float2 py = *reinterpret_cast<const float2*>(prev_y + 2 * b);
    const float cc = ccoarse[b];

    const __half* r0 = Rh + (size_t)b * H3;
    float Ru[4], Rr[4], Re[4];
    load4h(r0 + h, Ru);
    load4h(r0 + H_SZ + h, Rr);
    load4h(r0 + 2 * H_SZ + h, Re);

    float Iu[4], Ir[4], Ie[4];
    if (h < S_SZ) {
        const float4 wu0 = *reinterpret_cast<const float4*>(Icw + h);
        const float4 wu1 = *reinterpret_cast<const float4*>(Icw + S3 + h);
        const float4 wr0 = *reinterpret_cast<const float4*>(Icw + S_SZ + h);
        const float4 wr1 = *reinterpret_cast<const float4*>(Icw + S3 + S_SZ + h);
        const float4 we0 = *reinterpret_cast<const float4*>(Icw + 2 * S_SZ + h);
        const float4 we1 = *reinterpret_cast<const float4*>(Icw + S3 + 2 * S_SZ + h);
        const float* u0 = &wu0.x; const float* u1 = &wu1.x;
        const float* rr0 = &wr0.x; const float* rr1 = &wr1.x;
        const float* e0 = &we0.x; const float* e1 = &we1.x;
        #pragma unroll
        for (int j = 0; j < 4; ++j) {
            Iu[j] = py.x * u0[j] + py.y * u1[j];
            Ir[j] = py.x * rr0[j] + py.y * rr1[j];
            Ie[j] = py.x * e0[j] + py.y * e1[j];
        }
    } else {
        const int hh = h - S_SZ;
        const float4 wu0 = *reinterpret_cast<const float4*>(Ifw + hh);
        const float4 wu1 = *reinterpret_cast<const float4*>(Ifw + S3 + hh);
        const float4 wu2 = *reinterpret_cast<const float4*>(Ifw + 2 * S3 + hh);
        const float4 wr0 = *reinterpret_cast<const float4*>(Ifw + S_SZ + hh);
        const float4 wr1 = *reinterpret_cast<const float4*>(Ifw + S3 + S_SZ + hh);
        const float4 wr2 = *reinterpret_cast<const float4*>(Ifw + 2 * S3 + S_SZ + hh);
        const float4 we0 = *reinterpret_cast<const float4*>(Ifw + 2 * S_SZ + hh);
        const float4 we1 = *reinterpret_cast<const float4*>(Ifw + S3 + 2 * S_SZ + hh);
        const float4 we2 = *reinterpret_cast<const float4*>(Ifw + 2 * S3 + 2 * S_SZ + hh);
        const float* u0 = &wu0.x; const float* u1 = &wu1.x; const float* u2 = &wu2.x;
        const float* rr0 = &wr0.x; const float* rr1 = &wr1.x; const float* rr2 = &wr2.x;
        const float* e0 = &we0.x; const float* e1 = &we1.x; const float* e2 = &we2.x;
        #pragma unroll
        for (int j = 0; j < 4; ++j) {
            Iu[j] = py.x * u0[j] + py.y * u1[j] + cc * u2[j];
            Ir[j] = py.x * rr0[j] + py.y * rr1[j] + cc * rr2[j];
            Ie[j] = py.x * e0[j] + py.y * e1[j] + cc * e2[j];
        }
    }

    const float4 bu4 = *reinterpret_cast<const float4*>(bu + h);
    const float4 br4 = *reinterpret_cast<const float4*>(br + h);
    const float4 be4 = *reinterpret_cast<const float4*>(be + h);
    float ph[4];
    load4h(Ah + (size_t)b * H_SZ + h, ph);
    const float* bup = &bu4.x; const float* brp = &br4.x; const float* bep = &be4.x;

    float hv[4];
    #pragma unroll
    for (int j = 0; j < 4; ++j) {
        const float u = sigf(Ru[j] + Iu[j] + bup[j]);
        const float r = sigf(Rr[j] + Ir[j] + brp[j]);
        const float e = tanhfast(r * Re[j] + Ie[j] + bep[j]);
        hv[j] = u * ph[j] + (1.0f - u) * e;
    }

    *reinterpret_cast<float4*>(hidden + (size_t)b * H_SZ + h) =
        make_float4(hv[0], hv[1], hv[2], hv[3]);
    __half2* hap = reinterpret_cast<__half2*>(hA + (size_t)b * H_SZ + h);
    hap[0] = __floats2half2_rn(hv[0], hv[1]);
    hap[1] = __floats2half2_rn(hv[2], hv[3]);
}

// ---------------------------------------------------------------------------
// Launch
// ---------------------------------------------------------------------------
extern "C" void kernel_launch(void* const* d_in, const int* in_sizes, int n_in,
                              void* d_out, int out_size)
{
    const float* prev_y  = (const float*)d_in[0];
    const float* prev_h  = (const float*)d_in[1];
    const float* ccoarse = (const float*)d_in[2];
    const float* R_W     = (const float*)d_in[3];
    const float* Icw     = (const float*)d_in[4];
    const float* Ifw     = (const float*)d_in[5];
    const float* O1_W    = (const float*)d_in[6];
    const float* O1_b    = (const float*)d_in[7];
    const float* O2_W    = (const float*)d_in[8];
    const float* O2_b    = (const float*)d_in[9];
    const float* O3_W    = (const float*)d_in[10];
    const float* O3_b    = (const float*)d_in[11];
    const float* O4_W    = (const float*)d_in[12];
    const float* O4_b    = (const float*)d_in[13];
    const float* bu      = (const float*)d_in[14];
    const float* br      = (const float*)d_in[15];
    const float* be      = (const float*)d_in[16];

    float* out        = (float*)d_out;
    float* out_coarse = out;
    float* out_fine   = out + (size_t)B_SZ * Q_SZ;
    float* hidden     = out + (size_t)2 * B_SZ * Q_SZ;

    __half *Rh, *Ah, *hA, *hc, *hf, *RWt, *O1t, *O2t, *O3t, *O4t;
    cudaGetSymbolAddress((void**)&Rh,  g_Rh);
    cudaGetSymbolAddress((void**)&Ah,  g_Ah);
    cudaGetSymbolAddress((void**)&hA,  g_hA);
    cudaGetSymbolAddress((void**)&hc,  g_hc);
    cudaGetSymbolAddress((void**)&hf,  g_hf);
    cudaGetSymbolAddress((void**)&RWt, g_RWt);
    cudaGetSymbolAddress((void**)&O1t, g_O1t);
    cudaGetSymbolAddress((void**)&O2t, g_O2t);
    cudaGetSymbolAddress((void**)&O3t, g_O3t);
    cudaGetSymbolAddress((void**)&O4t, g_O4t);

    const int SMB128 = 2 * (128 + 128) * PW * 4;   // 73728
    const int SMB112 = 2 * (128 + 112) * PW * 4;   // 69120
    cudaFuncSetAttribute(hgemm<128, 0, 1, 0>, cudaFuncAttributeMaxDynamicSharedMemorySize, SMB128);
    cudaFuncSetAttribute(hgemm<112, 1, 1, 1>, cudaFuncAttributeMaxDynamicSharedMemorySize, SMB112);
    cudaFuncSetAttribute(hgemm<128, 2, 0, 1>, cudaFuncAttributeMaxDynamicSharedMemorySize, SMB128);

    // --- prep: ONE launch (f2h + all weight transposes) ---
    prep_all<<<NB_PREP, 256>>>(prev_h, Ah, R_W, RWt,
                               O1_W, O1t, O3_W, O3t, O2_W, O2t, O4_W, O4t);

    const int MT = B_SZ / 128;   // 256 M-tiles

    // 1) Rh = Ah @ RWt^T   (fp16 in, fp16 out)  N=2688=21x128 exact
    hgemm<128, 0, 1, 0><<<dim3(H3 / 128, MT, 1), 128, SMB128>>>(
        Ah, nullptr, H_SZ, RWt, nullptr, H_SZ, nullptr, nullptr,
        Rh, nullptr, H3, H_SZ);
    // 2) GRU gates -> hidden (fp32) + fp16 copy (prev_h via fp16 Ah)
    gru_elem4<<<(B_SZ * (H_SZ / 4) + 255) / 256, 256>>>(
        Rh, Ah, prev_y, ccoarse, Icw, Ifw, bu, br, be, hidden, hA);
    // 3+4) heads layer 1: N=448=4x112 exact (BN=112)
    hgemm<112, 1, 1, 1><<<dim3(S_SZ / 112, MT, 2), 128, SMB112>>>(
        hA, hA + S_SZ, H_SZ, O1t, O3t, S_SZ, O1_b, O3_b,
        hc, hf, S_SZ, S_SZ);
    // 5+6) heads layer 2: N=256=2x128 exact
    hgemm<128, 2, 0, 1><<<dim3(Q_SZ / 128, MT, 2), 128, SMB128>>>(
        hc, hf, S_SZ, O2t, O4t, S_SZ, O2_b, O4_b,
        out_coarse, out_fine, Q_SZ, S_SZ);
}

// round 15
// speedup vs baseline: 1.3136x; 1.0179x over previous
#include <cuda_runtime.h>
#include <cuda_fp16.h>
#include <math.h>
#include <stdint.h>

// Problem dims (fixed)
#define B_SZ 32768
#define H_SZ 896
#define S_SZ 448
#define Q_SZ 256
#define H3   2688
#define S3   1344

// ---------------------------------------------------------------------------
// Scratch (device globals; allocation-free per harness rules)
// ---------------------------------------------------------------------------
__device__ __half g_Rh [(size_t)B_SZ * H3];      // R_hidden fp16
__device__ __half g_Ah [(size_t)B_SZ * H_SZ];    // fp16 prev_hidden
__device__ __half g_hA [(size_t)B_SZ * H_SZ];    // fp16 hidden
__device__ __half g_hc [(size_t)B_SZ * S_SZ];
__device__ __half g_hf [(size_t)B_SZ * S_SZ];
__device__ __half g_RWt[(size_t)H3 * H_SZ];
__device__ __half g_O1t[S_SZ * S_SZ];
__device__ __half g_O2t[Q_SZ * S_SZ];
__device__ __half g_O3t[S_SZ * S_SZ];
__device__ __half g_O4t[Q_SZ * S_SZ];

// ---------------------------------------------------------------------------
// Helpers (non-arch-specific PTX only: must assemble for plain sm_103)
// ---------------------------------------------------------------------------
__device__ __forceinline__ uint32_t smem_u32(const void* p) {
    uint32_t a;
    asm("{ .reg .u64 t; cvta.to.shared.u64 t, %1; cvt.u32.u64 %0, t; }" : "=r"(a) : "l"(p));
    return a;
}
__device__ __forceinline__ void cp_async16(uint32_t s, const void* g) {
    asm volatile("cp.async.cg.shared.global [%0], [%1], 16;\n" :: "r"(s), "l"(g));
}
#define CP_COMMIT()  asm volatile("cp.async.commit_group;\n" ::)
#define CP_WAIT(n)   asm volatile("cp.async.wait_group %0;\n" :: "n"(n))

__device__ __forceinline__ void mma_16816(float* d, const uint32_t* a, const uint32_t* b) {
    asm volatile(
        "mma.sync.aligned.m16n8k16.row.col.f32.f16.f16.f32 "
        "{%0,%1,%2,%3}, {%4,%5,%6,%7}, {%8,%9}, {%0,%1,%2,%3};"
        : "+f"(d[0]), "+f"(d[1]), "+f"(d[2]), "+f"(d[3])
        : "r"(a[0]), "r"(a[1]), "r"(a[2]), "r"(a[3]), "r"(b[0]), "r"(b[1]));
}
__device__ __forceinline__ void ldsm4(uint32_t* r, uint32_t addr) {
    asm volatile("ldmatrix.sync.aligned.m8n8.x4.shared.b16 {%0,%1,%2,%3}, [%4];"
                 : "=r"(r[0]), "=r"(r[1]), "=r"(r[2]), "=r"(r[3]) : "r"(addr));
}

// ---------------------------------------------------------------------------
// fp16 mma.sync GEMM: C[M,N] = A[M,K] @ Bt[N,K]^T (+bias)(+relu)
// CTA tile 128 x BN (BN divides N exactly, BN % 32 == 0 -> no guards).
// 256 thr = 8 warps (2x4), warp tile 64 x (BN/4). BK=64 fp16.
// Fragments via ldmatrix.x4 (6 LDSM vs 48 LDS.32 per s-step per warp).
// EPI: 0=none, 1=bias+relu, 2=bias.  HOUT: 1 = __half C, 0 = float C.
// DUAL: blockIdx.z selects problem set.
// ---------------------------------------------------------------------------
#define PW 36                     // words (4B) per smem row: 64 halves + 16B pad

template <int BN, int EPI, int HOUT, int DUAL>
__global__ void __launch_bounds__(256, 2)
hgemm(const __half* __restrict__ A0, const __half* __restrict__ A1, int lda,
      const __half* __restrict__ B0, const __half* __restrict__ B1, int ldb,
      const float* __restrict__ bias0, const float* __restrict__ bias1,
      void* __restrict__ C0v, void* __restrict__ C1v, int ldc, int K)
{
    constexpr int AW   = 128 * PW;
    constexpr int BW   = BN * PW;
    constexpr int BUFW = AW + BW;
    constexpr int WN   = BN / 4;          // warp tile N
    constexpr int NF   = BN / 32;         // B n-fragments per warp (even)

    extern __shared__ uint32_t smw[];
    const __half* A    = (DUAL && blockIdx.z) ? A1 : A0;
    const __half* Bt   = (DUAL && blockIdx.z) ? B1 : B0;
    const float*  bias = (DUAL && blockIdx.z) ? bias1 : bias0;
    void*         Cv   = (DUAL && blockIdx.z) ? C1v : C0v;

    const int tid = threadIdx.x;
    const int lane = tid & 31, w = tid >> 5;
    const int wr = w >> 2, wc = w & 3;        // 2x4 warp grid
    const int lq = lane >> 2, ln = lane & 3;

    const int rowBase = blockIdx.y * 128;
    const int colBase = blockIdx.x * BN;

    const uint32_t sBase = smem_u32(smw);

    // cp.async mapping: chunk c = tid + i*256 -> row c>>3 (32/iter), col16 c&7
    const int r0 = tid >> 3, c16 = tid & 7;
    const uint32_t dstOff = (uint32_t)((r0 * PW + c16 * 4) * 4);
    const __half* Abase = A + (size_t)(rowBase + r0) * lda + c16 * 8;
    const __half* Bbase = Bt + (size_t)(colBase + r0) * ldb + c16 * 8;

    auto load_tile = [&](int buf, int it) {
        const int kb = it * 64;
        const uint32_t base = sBase + (uint32_t)(buf * BUFW * 4);
        #pragma unroll
        for (int i = 0; i < 4; ++i)
            cp_async16(base + dstOff + (uint32_t)(i * 32 * PW * 4),
                       Abase + kb + (size_t)(i * 32) * lda);
        #pragma unroll
        for (int i = 0; i < BN * 8 / 256; ++i)
            cp_async16(base + (uint32_t)(AW * 4) + dstOff + (uint32_t)(i * 32 * PW * 4),
                       Bbase + kb + (size_t)(i * 32) * ldb);
        CP_COMMIT();
    };

    // ldmatrix per-lane base offsets (bytes, within buffer)
    const int g = lane >> 3;
    const uint32_t aLB = (uint32_t)((wr * 64 + (lane & 7) + (g & 1) * 8) * PW * 4)
                       + (uint32_t)((g >> 1) * 16);
    const uint32_t bLB = (uint32_t)(AW * 4)
                       + (uint32_t)((wc * WN + (lane & 7) + (g >> 1) * 8) * PW * 4)
                       + (uint32_t)((g & 1) * 16);

    float acc[4][NF][4];
    #pragma unroll
    for (int i = 0; i < 4; ++i)
        #pragma unroll
        for (int j = 0; j < NF; ++j)
            #pragma unroll
            for (int k = 0; k < 4; ++k) acc[i][j][k] = 0.0f;

    const int nit = K >> 6;
    load_tile(0, 0);

    for (int it = 0; it < nit; ++it) {
        const int buf = it & 1;
        if (it + 1 < nit) { load_tile(buf ^ 1, it + 1); CP_WAIT(1); }
        else              { CP_WAIT(0); }
        __syncthreads();

        const uint32_t bufB = sBase + (uint32_t)(buf * BUFW * 4);

        #pragma unroll
        for (int s = 0; s < 4; ++s) {          // 4 x K=16 steps
            uint32_t a[4][4], b[NF][2];
            #pragma unroll
            for (int mf = 0; mf < 4; ++mf)
                ldsm4(a[mf], bufB + aLB + (uint32_t)(mf * 16 * PW * 4) + (uint32_t)(s * 32));
            #pragma unroll
            for (int p = 0; p < NF / 2; ++p) {
                uint32_t t4[4];
                ldsm4(t4, bufB + bLB + (uint32_t)(p * 16 * PW * 4) + (uint32_t)(s * 32));
                b[2 * p][0] = t4[0]; b[2 * p][1] = t4[1];
                b[2 * p + 1][0] = t4[2]; b[2 * p + 1][1] = t4[3];
            }
            #pragma unroll
            for (int mf = 0; mf < 4; ++mf)
                #pragma unroll
                for (int nf = 0; nf < NF; ++nf)
                    mma_16816(acc[mf][nf], a[mf], b[nf]);
        }
        __syncthreads();
    }

    // ---- epilogue (exact tiling, no guards) ----
    #pragma unroll
    for (int nf = 0; nf < NF; ++nf) {
        const int col = colBase + wc * WN + nf * 8 + ln * 2;
        float2 bv = make_float2(0.0f, 0.0f);
        if (EPI) bv = *reinterpret_cast<const float2*>(bias + col);
        #pragma unroll
        for (int mf = 0; mf < 4; ++mf) {
            const int row = rowBase + wr * 64 + mf * 16 + lq;
            float2 v0 = make_float2(acc[mf][nf][0], acc[mf][nf][1]);
            float2 v1 = make_float2(acc[mf][nf][2], acc[mf][nf][3]);
            if (EPI) {
                v0.x += bv.x; v0.y += bv.y; v1.x += bv.x; v1.y += bv.y;
                if (EPI == 1) {
                    v0.x = fmaxf(v0.x, 0.0f); v0.y = fmaxf(v0.y, 0.0f);
                    v1.x = fmaxf(v1.x, 0.0f); v1.y = fmaxf(v1.y, 0.0f);
                }
            }
            if (HOUT) {
                __half* Ch = (__half*)Cv;
                *reinterpret_cast<__half2*>(Ch + (size_t)row * ldc + col) =
                    __floats2half2_rn(v0.x, v0.y);
                *reinterpret_cast<__half2*>(Ch + (size_t)(row + 8) * ldc + col) =
                    __floats2half2_rn(v1.x, v1.y);
            } else {
                float* Cf = (float*)Cv;
                *reinterpret_cast<float2*>(Cf + (size_t)row * ldc + col) = v0;
                *reinterpret_cast<float2*>(Cf + (size_t)(row + 8) * ldc + col) = v1;
            }
        }
    }
}

// ---------------------------------------------------------------------------
// Mega-prep: ONE launch. Block-range dispatch (same as R14).
// ---------------------------------------------------------------------------
#define NB_F2H  (B_SZ * H_SZ / 8 / 256)            // 14336
#define NB_RW   ((H3 / 32) * (H_SZ / 32))          // 2352
#define NB_O13  (2 * (S_SZ / 32) * (S_SZ / 32))    // 392
#define NB_O24  (2 * (Q_SZ / 32) * (S_SZ / 32))    // 224
#define NB_PREP (NB_F2H + NB_RW + NB_O13 + NB_O24)

__device__ __forceinline__ void transpose_body(
    const float* __restrict__ in, __half* __restrict__ out,
    int K, int N, int bx, int by, int tid, float (*t)[33])
{
    const int n0 = bx * 32, k0 = by * 32;
    const int tx = tid & 31, ty = tid >> 5;   // 32 x 8
    #pragma unroll
    for (int j = 0; j < 32; j += 8)
        t[ty + j][tx] = in[(size_t)(k0 + ty + j) * N + n0 + tx];
    __syncthreads();
    #pragma unroll
    for (int j = 0; j < 32; j += 8)
        out[(size_t)(n0 + ty + j) * K + k0 + tx] = __float2half_rn(t[tx][ty + j]);
}

__global__ void __launch_bounds__(256)
prep_all(const float* __restrict__ prev_h, __half* __restrict__ Ah,
         const float* __restrict__ R_W,  __half* __restrict__ RWt,
         const float* __restrict__ O1_W, __half* __restrict__ O1t,
         const float* __restrict__ O3_W, __half* __restrict__ O3t,
         const float* __restrict__ O2_W, __half* __restrict__ O2t,
         const float* __restrict__ O4_W, __half* __restrict__ O4t)
{
    __shared__ float t[32][33];
    const int tid = threadIdx.x;
    int b = blockIdx.x;

    if (b < NB_F2H) {
        const int i = b * 256 + tid;
        const float4* in = (const float4*)prev_h;
        __half2* out = (__half2*)Ah;
        float4 v0 = in[2 * i], v1 = in[2 * i + 1];
        out[4 * i]     = __floats2half2_rn(v0.x, v0.y);
        out[4 * i + 1] = __floats2half2_rn(v0.z, v0.w);
        out[4 * i + 2] = __floats2half2_rn(v1.x, v1.y);
        out[4 * i + 3] = __floats2half2_rn(v1.z, v1.w);
        return;
    }
    b -= NB_F2H;
    if (b < NB_RW) {
        transpose_body(R_W, RWt, H_SZ, H3, b % (H3 / 32), b / (H3 / 32), tid, t);
        return;
    }
    b -= NB_RW;
    if (b < NB_O13) {
        const int half = NB_O13 / 2;
        const float* in  = (b < half) ? O1_W : O3_W;
        __half*      out = (b < half) ? O1t  : O3t;
        const int bb = (b < half) ? b : b - half;
        transpose_body(in, out, S_SZ, S_SZ, bb % (S_SZ / 32), bb / (S_SZ / 32), tid, t);
        return;
    }
    b -= NB_O13;
    {
        const int half = NB_O24 / 2;
        const float* in  = (b < half) ? O2_W : O4_W;
        __half*      out = (b < half) ? O2t  : O4t;
        const int bb = (b < half) ? b : b - half;
        transpose_body(in, out, S_SZ, Q_SZ, bb % (Q_SZ / 32), bb / (Q_SZ / 32), tid, t);
    }
}

// ---------------------------------------------------------------------------
// GRU gate elementwise, 4 h per thread; prev_h read as fp16 (Ah)
// ---------------------------------------------------------------------------
__device__ __forceinline__ void load4h(const __half* p, float* o) {
    const __half2 v0 = *reinterpret_cast<const __half2*>(p);
    const __half2 v1 = *reinterpret_cast<const __half2*>(p + 2);
    const float2 f0 = __half22float2(v0), f1 = __half22float2(v1);
    o[0] = f0.x; o[1] = f0.y; o[2] = f1.x; o[3] = f1.y;
}
__device__ __forceinline__ float sigf(float x) {
    return 1.0f / (1.0f + __expf(-x));
}
__device__ __forceinline__ float tanhfast(float x) {
    return 2.0f / (1.0f + __expf(-2.0f * x)) - 1.0f;
}

__global__ void gru_elem4(const __half* __restrict__ Rh, const __half* __restrict__ Ah,
                          const float* __restrict__ prev_y, const float* __restrict__ ccoarse,
                          const float* __restrict__ Icw, const float* __restrict__ Ifw,
                          const float* __restrict__ bu, const float* __restrict__ br,
                          const float* __restrict__ be,
                          float* __restrict__ hidden, __half* __restrict__ hA) {
    const int idx = blockIdx.x * blockDim.x + threadIdx.x;
    if (idx >= B_SZ * (H_SZ / 4)) return;
    const int b = idx / (H_SZ / 4);
    const int h = (idx - b * (H_SZ / 4)) * 4;

    const float2 py = *reinterpret_cast<const float2*>(prev_y + 2 * b);
    const float cc = ccoarse[b];

    const __half* r0 = Rh + (size_t)b * H3;
    float Ru[4], Rr[4], Re[4];
    load4h(r0 + h, Ru);
    load4h(r0 + H_SZ + h, Rr);
    load4h(r0 + 2 * H_SZ + h, Re);

    float Iu[4], Ir[4], Ie[4];
    if (h < S_SZ) {
        const float4 wu0 = *reinterpret_cast<const float4*>(Icw + h);
        const float4 wu1 = *reinterpret_cast<const float4*>(Icw + S3 + h);
        const float4 wr0 = *reinterpret_cast<const float4*>(Icw + S_SZ + h);
        const float4 wr1 = *reinterpret_cast<const float4*>(Icw + S3 + S_SZ + h);
        const float4 we0 = *reinterpret_cast<const float4*>(Icw + 2 * S_SZ + h);
        const float4 we1 = *reinterpret_cast<const float4*>(Icw + S3 + 2 * S_SZ + h);
        const float* u0 = &wu0.x; const float* u1 = &wu1.x;
        const float* rr0 = &wr0.x; const float* rr1 = &wr1.x;
        const float* e0 = &we0.x; const float* e1 = &we1.x;
        #pragma unroll
        for (int j = 0; j < 4; ++j) {
            Iu[j] = py.x * u0[j] + py.y * u1[j];
            Ir[j] = py.x * rr0[j] + py.y * rr1[j];
            Ie[j] = py.x * e0[j] + py.y * e1[j];
        }
    } else {
        const int hh = h - S_SZ;
        const float4 wu0 = *reinterpret_cast<const float4*>(Ifw + hh);
        const float4 wu1 = *reinterpret_cast<const float4*>(Ifw + S3 + hh);
        const float4 wu2 = *reinterpret_cast<const float4*>(Ifw + 2 * S3 + hh);
        const float4 wr0 = *reinterpret_cast<const float4*>(Ifw + S_SZ + hh);
        const float4 wr1 = *reinterpret_cast<const float4*>(Ifw + S3 + S_SZ + hh);
        const float4 wr2 = *reinterpret_cast<const float4*>(Ifw + 2 * S3 + S_SZ + hh);
        const float4 we0 = *reinterpret_cast<const float4*>(Ifw + 2 * S_SZ + hh);
        const float4 we1 = *reinterpret_cast<const float4*>(Ifw + S3 + 2 * S_SZ + hh);
        const float4 we2 = *reinterpret_cast<const float4*>(Ifw + 2 * S3 + 2 * S_SZ + hh);
        const float* u0 = &wu0.x; const float* u1 = &wu1.x; const float* u2 = &wu2.x;
        const float* rr0 = &wr0.x; const float* rr1 = &wr1.x; const float* rr2 = &wr2.x;
        const float* e0 = &we0.x; const float* e1 = &we1.x; const float* e2 = &we2.x;
        #pragma unroll
        for (int j = 0; j < 4; ++j) {
            Iu[j] = py.x * u0[j] + py.y * u1[j] + cc * u2[j];
            Ir[j] = py.x * rr0[j] + py.y * rr1[j] + cc * rr2[j];
            Ie[j] = py.x * e0[j] + py.y * e1[j] + cc * e2[j];
        }
    }

    const float4 bu4 = *reinterpret_cast<const float4*>(bu + h);
    const float4 br4 = *reinterpret_cast<const float4*>(br + h);
    const float4 be4 = *reinterpret_cast<const float4*>(be + h);
    float ph[4];
    load4h(Ah + (size_t)b * H_SZ + h, ph);
    const float* bup = &bu4.x; const float* brp = &br4.x; const float* bep = &be4.x;

    float hv[4];
    #pragma unroll
    for (int j = 0; j < 4; ++j) {
        const float u = sigf(Ru[j] + Iu[j] + bup[j]);
        const float r = sigf(Rr[j] + Ir[j] + brp[j]);
        const float e = tanhfast(r * Re[j] + Ie[j] + bep[j]);
        hv[j] = u * ph[j] + (1.0f - u) * e;
    }

    *reinterpret_cast<float4*>(hidden + (size_t)b * H_SZ + h) =
        make_float4(hv[0], hv[1], hv[2], hv[3]);
    __half2* hap = reinterpret_cast<__half2*>(hA + (size_t)b * H_SZ + h);
    hap[0] = __floats2half2_rn(hv[0], hv[1]);
    hap[1] = __floats2half2_rn(hv[2], hv[3]);
}

// ---------------------------------------------------------------------------
// Launch
// ---------------------------------------------------------------------------
extern "C" void kernel_launch(void* const* d_in, const int* in_sizes, int n_in,
                              void* d_out, int out_size)
{
    const float* prev_y  = (const float*)d_in[0];
    const float* prev_h  = (const float*)d_in[1];
    const float* ccoarse = (const float*)d_in[2];
    const float* R_W     = (const float*)d_in[3];
    const float* Icw     = (const float*)d_in[4];
    const float* Ifw     = (const float*)d_in[5];
    const float* O1_W    = (const float*)d_in[6];
    const float* O1_b    = (const float*)d_in[7];
    const float* O2_W    = (const float*)d_in[8];
    const float* O2_b    = (const float*)d_in[9];
    const float* O3_W    = (const float*)d_in[10];
    const float* O3_b    = (const float*)d_in[11];
    const float* O4_W    = (const float*)d_in[12];
    const float* O4_b    = (const float*)d_in[13];
    const float* bu      = (const float*)d_in[14];
    const float* br      = (const float*)d_in[15];
    const float* be      = (const float*)d_in[16];

    float* out        = (float*)d_out;
    float* out_coarse = out;
    float* out_fine   = out + (size_t)B_SZ * Q_SZ;
    float* hidden     = out + (size_t)2 * B_SZ * Q_SZ;

    __half *Rh, *Ah, *hA, *hc, *hf, *RWt, *O1t, *O2t, *O3t, *O4t;
    cudaGetSymbolAddress((void**)&Rh,  g_Rh);
    cudaGetSymbolAddress((void**)&Ah,  g_Ah);
    cudaGetSymbolAddress((void**)&hA,  g_hA);
    cudaGetSymbolAddress((void**)&hc,  g_hc);
    cudaGetSymbolAddress((void**)&hf,  g_hf);
    cudaGetSymbolAddress((void**)&RWt, g_RWt);
    cudaGetSymbolAddress((void**)&O1t, g_O1t);
    cudaGetSymbolAddress((void**)&O2t, g_O2t);
    cudaGetSymbolAddress((void**)&O3t, g_O3t);
    cudaGetSymbolAddress((void**)&O4t, g_O4t);

    const int SMB128 = 2 * (128 + 128) * PW * 4;   // 73728
    const int SMB64  = 2 * (128 + 64) * PW * 4;    // 55296
    cudaFuncSetAttribute(hgemm<128, 0, 1, 0>, cudaFuncAttributeMaxDynamicSharedMemorySize, SMB128);
    cudaFuncSetAttribute(hgemm<64, 1, 1, 1>,  cudaFuncAttributeMaxDynamicSharedMemorySize, SMB64);
    cudaFuncSetAttribute(hgemm<128, 2, 0, 1>, cudaFuncAttributeMaxDynamicSharedMemorySize, SMB128);

    // --- prep: ONE launch (f2h + all weight transposes) ---
    prep_all<<<NB_PREP, 256>>>(prev_h, Ah, R_W, RWt,
                               O1_W, O1t, O3_W, O3t, O2_W, O2t, O4_W, O4t);

    const int MT = B_SZ / 128;   // 256 M-tiles

    // 1) Rh = Ah @ RWt^T   (fp16 in, fp16 out)  N=2688=21x128 exact
    hgemm<128, 0, 1, 0><<<dim3(H3 / 128, MT, 1), 256, SMB128>>>(
        Ah, nullptr, H_SZ, RWt, nullptr, H_SZ, nullptr, nullptr,
        Rh, nullptr, H3, H_SZ);
    // 2) GRU gates -> hidden (fp32) + fp16 copy
    gru_elem4<<<(B_SZ * (H_SZ / 4) + 255) / 256, 256>>>(
        Rh, Ah, prev_y, ccoarse, Icw, Ifw, bu, br, be, hidden, hA);
    // 3+4) heads layer 1: N=448=7x64 exact (BN=64)
    hgemm<64, 1, 1, 1><<<dim3(S_SZ / 64, MT, 2), 256, SMB64>>>(
        hA, hA + S_SZ, H_SZ, O1t, O3t, S_SZ, O1_b, O3_b,
        hc, hf, S_SZ, S_SZ);
    // 5+6) heads layer 2: N=256=2x128 exact
    hgemm<128, 2, 0, 1><<<dim3(Q_SZ / 128, MT, 2), 256, SMB128>>>(
        hc, hf, S_SZ, O2t, O4t, S_SZ, O2_b, O4_b,
        out_coarse, out_fine, Q_SZ, S_SZ);
}

// round 16
// speedup vs baseline: 1.3434x; 1.0227x over previous
#include <cuda_runtime.h>
#include <cuda_fp16.h>
#include <math.h>
#include <stdint.h>

// Problem dims (fixed)
#define B_SZ 32768
#define H_SZ 896
#define S_SZ 448
#define Q_SZ 256
#define H3   2688
#define S3   1344

// ---------------------------------------------------------------------------
// Scratch (device globals; allocation-free per harness rules)
// ---------------------------------------------------------------------------
__device__ __half g_Rh [(size_t)B_SZ * H3];      // R_hidden fp16
__device__ __half g_Ah [(size_t)B_SZ * H_SZ];    // fp16 prev_hidden
__device__ __half g_hA [(size_t)B_SZ * H_SZ];    // fp16 hidden
__device__ __half g_hc [(size_t)B_SZ * S_SZ];
__device__ __half g_hf [(size_t)B_SZ * S_SZ];
__device__ __half g_RWt[(size_t)H3 * H_SZ];
__device__ __half g_O1t[S_SZ * S_SZ];
__device__ __half g_O2t[Q_SZ * S_SZ];
__device__ __half g_O3t[S_SZ * S_SZ];
__device__ __half g_O4t[Q_SZ * S_SZ];

// ---------------------------------------------------------------------------
// Helpers (non-arch-specific PTX only: must assemble for plain sm_103)
// ---------------------------------------------------------------------------
__device__ __forceinline__ uint32_t smem_u32(const void* p) {
    uint32_t a;
    asm("{ .reg .u64 t; cvta.to.shared.u64 t, %1; cvt.u32.u64 %0, t; }" : "=r"(a) : "l"(p));
    return a;
}
__device__ __forceinline__ void cp_async16(uint32_t s, const void* g) {
    asm volatile("cp.async.cg.shared.global [%0], [%1], 16;\n" :: "r"(s), "l"(g));
}
#define CP_COMMIT()  asm volatile("cp.async.commit_group;\n" ::)
#define CP_WAIT(n)   asm volatile("cp.async.wait_group %0;\n" :: "n"(n))

__device__ __forceinline__ void mma_16816(float* d, const uint32_t* a, const uint32_t* b) {
    asm volatile(
        "mma.sync.aligned.m16n8k16.row.col.f32.f16.f16.f32 "
        "{%0,%1,%2,%3}, {%4,%5,%6,%7}, {%8,%9}, {%0,%1,%2,%3};"
        : "+f"(d[0]), "+f"(d[1]), "+f"(d[2]), "+f"(d[3])
        : "r"(a[0]), "r"(a[1]), "r"(a[2]), "r"(a[3]), "r"(b[0]), "r"(b[1]));
}
__device__ __forceinline__ void ldsm4(uint32_t* r, uint32_t addr) {
    asm volatile("ldmatrix.sync.aligned.m8n8.x4.shared.b16 {%0,%1,%2,%3}, [%4];"
                 : "=r"(r[0]), "=r"(r[1]), "=r"(r[2]), "=r"(r[3]) : "r"(addr));
}
__device__ __forceinline__ void ldsm2(uint32_t* r, uint32_t addr) {
    asm volatile("ldmatrix.sync.aligned.m8n8.x2.shared.b16 {%0,%1}, [%2];"
                 : "=r"(r[0]), "=r"(r[1]) : "r"(addr));
}

// ---------------------------------------------------------------------------
// fp16 mma.sync GEMM: C[M,N] = A[M,K] @ Bt[N,K]^T (+bias)(+relu)
// CTA tile 128 x BN (BN divides N exactly, BN % 32 == 0 -> no guards).
// 256 thr = 8 warps (2x4), warp tile 64 x (BN/4). BK=64 fp16.
// Fragments via ldmatrix (x4 pairs; x2 tail when NF odd).
// EPI: 0=none, 1=bias+relu, 2=bias.  HOUT: 1 = __half C, 0 = float C.
// DUAL: blockIdx.z selects problem set.  MINCTA: launch-bounds min blocks.
// ---------------------------------------------------------------------------
#define PW 36                     // words (4B) per smem row: 64 halves + 16B pad

template <int BN, int EPI, int HOUT, int DUAL, int MINCTA>
__global__ void __launch_bounds__(256, MINCTA)
hgemm(const __half* __restrict__ A0, const __half* __restrict__ A1, int lda,
      const __half* __restrict__ B0, const __half* __restrict__ B1, int ldb,
      const float* __restrict__ bias0, const float* __restrict__ bias1,
      void* __restrict__ C0v, void* __restrict__ C1v, int ldc, int K)
{
    constexpr int AW   = 128 * PW;
    constexpr int BW   = BN * PW;
    constexpr int BUFW = AW + BW;
    constexpr int WN   = BN / 4;          // warp tile N
    constexpr int NF   = BN / 32;         // B n-fragments per warp

    extern __shared__ uint32_t smw[];
    const __half* A    = (DUAL && blockIdx.z) ? A1 : A0;
    const __half* Bt   = (DUAL && blockIdx.z) ? B1 : B0;
    const float*  bias = (DUAL && blockIdx.z) ? bias1 : bias0;
    void*         Cv   = (DUAL && blockIdx.z) ? C1v : C0v;

    const int tid = threadIdx.x;
    const int lane = tid & 31, w = tid >> 5;
    const int wr = w >> 2, wc = w & 3;        // 2x4 warp grid
    const int lq = lane >> 2, ln = lane & 3;

    const int rowBase = blockIdx.y * 128;
    const int colBase = blockIdx.x * BN;

    const uint32_t sBase = smem_u32(smw);

    // cp.async mapping: chunk c = tid + i*256 -> row c>>3 (32/iter), col16 c&7
    const int r0 = tid >> 3, c16 = tid & 7;
    const uint32_t dstOff = (uint32_t)((r0 * PW + c16 * 4) * 4);
    const __half* Abase = A + (size_t)(rowBase + r0) * lda + c16 * 8;
    const __half* Bbase = Bt + (size_t)(colBase + r0) * ldb + c16 * 8;

    auto load_tile = [&](int buf, int it) {
        const int kb = it * 64;
        const uint32_t base = sBase + (uint32_t)(buf * BUFW * 4);
        #pragma unroll
        for (int i = 0; i < 4; ++i)
            cp_async16(base + dstOff + (uint32_t)(i * 32 * PW * 4),
                       Abase + kb + (size_t)(i * 32) * lda);
        #pragma unroll
        for (int i = 0; i < BN * 8 / 256; ++i)
            cp_async16(base + (uint32_t)(AW * 4) + dstOff + (uint32_t)(i * 32 * PW * 4),
                       Bbase + kb + (size_t)(i * 32) * ldb);
        CP_COMMIT();
    };

    // ldmatrix per-lane base offsets (bytes, within buffer)
    const int g = lane >> 3;
    const uint32_t aLB = (uint32_t)((wr * 64 + (lane & 7) + (g & 1) * 8) * PW * 4)
                       + (uint32_t)((g >> 1) * 16);
    const uint32_t bLB = (uint32_t)(AW * 4)
                       + (uint32_t)((wc * WN + (lane & 7) + (g >> 1) * 8) * PW * 4)
                       + (uint32_t)((g & 1) * 16);
    // x2 tail (odd NF): lanes 0-15 supply addresses; matrix0 = k0-7, matrix1 = k8-15
    const uint32_t bLB2 = (uint32_t)(AW * 4)
                        + (uint32_t)((wc * WN + (NF - 1) * 8 + (lane & 7)) * PW * 4)
                        + (uint32_t)(((lane >> 3) & 1) * 16);

    float acc[4][NF][4];
    #pragma unroll
    for (int i = 0; i < 4; ++i)
        #pragma unroll
        for (int j = 0; j < NF; ++j)
            #pragma unroll
            for (int k = 0; k < 4; ++k) acc[i][j][k] = 0.0f;

    const int nit = K >> 6;
    load_tile(0, 0);

    for (int it = 0; it < nit; ++it) {
        const int buf = it & 1;
        if (it + 1 < nit) { load_tile(buf ^ 1, it + 1); CP_WAIT(1); }
        else              { CP_WAIT(0); }
        __syncthreads();

        const uint32_t bufB = sBase + (uint32_t)(buf * BUFW * 4);

        #pragma unroll
        for (int s = 0; s < 4; ++s) {          // 4 x K=16 steps
            uint32_t a[4][4], b[NF][2];
            #pragma unroll
            for (int mf = 0; mf < 4; ++mf)
                ldsm4(a[mf], bufB + aLB + (uint32_t)(mf * 16 * PW * 4) + (uint32_t)(s * 32));
            #pragma unroll
            for (int p = 0; p < NF / 2; ++p) {
                uint32_t t4[4];
                ldsm4(t4, bufB + bLB + (uint32_t)(p * 16 * PW * 4) + (uint32_t)(s * 32));
                b[2 * p][0] = t4[0]; b[2 * p][1] = t4[1];
                b[2 * p + 1][0] = t4[2]; b[2 * p + 1][1] = t4[3];
            }
            if (NF & 1) {
                ldsm2(b[NF - 1], bufB + bLB2 + (uint32_t)(s * 32));
            }
            #pragma unroll
            for (int mf = 0; mf < 4; ++mf)
                #pragma unroll
                for (int nf = 0; nf < NF; ++nf)
                    mma_16816(acc[mf][nf], a[mf], b[nf]);
        }
        __syncthreads();
    }

    // ---- epilogue (exact tiling, no guards) ----
    #pragma unroll
    for (int nf = 0; nf < NF; ++nf) {
        const int col = colBase + wc * WN + nf * 8 + ln * 2;
        float2 bv = make_float2(0.0f, 0.0f);
        if (EPI) bv = *reinterpret_cast<const float2*>(bias + col);
        #pragma unroll
        for (int mf = 0; mf < 4; ++mf) {
            const int row = rowBase + wr * 64 + mf * 16 + lq;
            float2 v0 = make_float2(acc[mf][nf][0], acc[mf][nf][1]);
            float2 v1 = make_float2(acc[mf][nf][2], acc[mf][nf][3]);
            if (EPI) {
                v0.x += bv.x; v0.y += bv.y; v1.x += bv.x; v1.y += bv.y;
                if (EPI == 1) {
                    v0.x = fmaxf(v0.x, 0.0f); v0.y = fmaxf(v0.y, 0.0f);
                    v1.x = fmaxf(v1.x, 0.0f); v1.y = fmaxf(v1.y, 0.0f);
                }
            }
            if (HOUT) {
                __half* Ch = (__half*)Cv;
                *reinterpret_cast<__half2*>(Ch + (size_t)row * ldc + col) =
                    __floats2half2_rn(v0.x, v0.y);
                *reinterpret_cast<__half2*>(Ch + (size_t)(row + 8) * ldc + col) =
                    __floats2half2_rn(v1.x, v1.y);
            } else {
                float* Cf = (float*)Cv;
                *reinterpret_cast<float2*>(Cf + (size_t)row * ldc + col) = v0;
                *reinterpret_cast<float2*>(Cf + (size_t)(row + 8) * ldc + col) = v1;
            }
        }
    }
}

// ---------------------------------------------------------------------------
// Mega-prep: ONE launch. Block-range dispatch.
// ---------------------------------------------------------------------------
#define NB_F2H  (B_SZ * H_SZ / 8 / 256)            // 14336
#define NB_RW   ((H3 / 32) * (H_SZ / 32))          // 2352
#define NB_O13  (2 * (S_SZ / 32) * (S_SZ / 32))    // 392
#define NB_O24  (2 * (Q_SZ / 32) * (S_SZ / 32))    // 224
#define NB_PREP (NB_F2H + NB_RW + NB_O13 + NB_O24)

__device__ __forceinline__ void transpose_body(
    const float* __restrict__ in, __half* __restrict__ out,
    int K, int N, int bx, int by, int tid, float (*t)[33])
{
    const int n0 = bx * 32, k0 = by * 32;
    const int tx = tid & 31, ty = tid >> 5;   // 32 x 8
    #pragma unroll
    for (int j = 0; j < 32; j += 8)
        t[ty + j][tx] = in[(size_t)(k0 + ty + j) * N + n0 + tx];
    __syncthreads();
    #pragma unroll
    for (int j = 0; j < 32; j += 8)
        out[(size_t)(n0 + ty + j) * K + k0 + tx] = __float2half_rn(t[tx][ty + j]);
}

__global__ void __launch_bounds__(256)
prep_all(const float* __restrict__ prev_h, __half* __restrict__ Ah,
         const float* __restrict__ R_W,  __half* __restrict__ RWt,
         const float* __restrict__ O1_W, __half* __restrict__ O1t,
         const float* __restrict__ O3_W, __half* __restrict__ O3t,
         const float* __restrict__ O2_W, __half* __restrict__ O2t,
         const float* __restrict__ O4_W, __half* __restrict__ O4t)
{
    __shared__ float t[32][33];
    const int tid = threadIdx.x;
    int b = blockIdx.x;

    if (b < NB_F2H) {
        const int i = b * 256 + tid;
        const float4* in = (const float4*)prev_h;
        __half2* out = (__half2*)Ah;
        float4 v0 = in[2 * i], v1 = in[2 * i + 1];
        out[4 * i]     = __floats2half2_rn(v0.x, v0.y);
        out[4 * i + 1] = __floats2half2_rn(v0.z, v0.w);
        out[4 * i + 2] = __floats2half2_rn(v1.x, v1.y);
        out[4 * i + 3] = __floats2half2_rn(v1.z, v1.w);
        return;
    }
    b -= NB_F2H;
    if (b < NB_RW) {
        transpose_body(R_W, RWt, H_SZ, H3, b % (H3 / 32), b / (H3 / 32), tid, t);
        return;
    }
    b -= NB_RW;
    if (b < NB_O13) {
        const int half = NB_O13 / 2;
        const float* in  = (b < half) ? O1_W : O3_W;
        __half*      out = (b < half) ? O1t  : O3t;
        const int bb = (b < half) ? b : b - half;
        transpose_body(in, out, S_SZ, S_SZ, bb % (S_SZ / 32), bb / (S_SZ / 32), tid, t);
        return;
    }
    b -= NB_O13;
    {
        const int half = NB_O24 / 2;
        const float* in  = (b < half) ? O2_W : O4_W;
        __half*      out = (b < half) ? O2t  : O4t;
        const int bb = (b < half) ? b : b - half;
        transpose_body(in, out, S_SZ, Q_SZ, bb % (Q_SZ / 32), bb / (Q_SZ / 32), tid, t);
    }
}

// ---------------------------------------------------------------------------
// GRU gate elementwise, 4 h per thread; prev_h read as fp16 (Ah)
// ---------------------------------------------------------------------------
__device__ __forceinline__ void load4h(const __half* p, float* o) {
    const __half2 v0 = *reinterpret_cast<const __half2*>(p);
    const __half2 v1 = *reinterpret_cast<const __half2*>(p + 2);
    const float2 f0 = __half22float2(v0), f1 = __half22float2(v1);
    o[0] = f0.x; o[1] = f0.y; o[2] = f1.x; o[3] = f1.y;
}
__device__ __forceinline__ float sigf(float x) {
    return 1.0f / (1.0f + __expf(-x));
}
__device__ __forceinline__ float tanhfast(float x) {
    return 2.0f / (1.0f + __expf(-2.0f * x)) - 1.0f;
}

__global__ void gru_elem4(const __half* __restrict__ Rh, const __half* __restrict__ Ah,
                          const float* __restrict__ prev_y, const float* __restrict__ ccoarse,
                          const float* __restrict__ Icw, const float* __restrict__ Ifw,
                          const float* __restrict__ bu, const float* __restrict__ br,
                          const float* __restrict__ be,
                          float* __restrict__ hidden, __half* __restrict__ hA) {
    const int idx = blockIdx.x * blockDim.x + threadIdx.x;
    if (idx >= B_SZ * (H_SZ / 4)) return;
    const int b = idx / (H_SZ / 4);
    const int h = (idx - b * (H_SZ / 4)) * 4;

    const float2 py = *reinterpret_cast<const float2*>(prev_y + 2 * b);
    const float cc = ccoarse[b];

    const __half* r0 = Rh + (size_t)b * H3;
    float Ru[4], Rr[4], Re[4];
    load4h(r0 + h, Ru);
    load4h(r0 + H_SZ + h, Rr);
    load4h(r0 + 2 * H_SZ + h, Re);

    float Iu[4], Ir[4], Ie[4];
    if (h < S_SZ) {
        const float4 wu0 = *reinterpret_cast<const float4*>(Icw + h);
        const float4 wu1 = *reinterpret_cast<const float4*>(Icw + S3 + h);
        const float4 wr0 = *reinterpret_cast<const float4*>(Icw + S_SZ + h);
        const float4 wr1 = *reinterpret_cast<const float4*>(Icw + S3 + S_SZ + h);
        const float4 we0 = *reinterpret_cast<const float4*>(Icw + 2 * S_SZ + h);
        const float4 we1 = *reinterpret_cast<const float4*>(Icw + S3 + 2 * S_SZ + h);
        const float* u0 = &wu0.x; const float* u1 = &wu1.x;
        const float* rr0 = &wr0.x; const float* rr1 = &wr1.x;
        const float* e0 = &we0.x; const float* e1 = &we1.x;
        #pragma unroll
        for (int j = 0; j < 4; ++j) {
            Iu[j] = py.x * u0[j] + py.y * u1[j];
            Ir[j] = py.x * rr0[j] + py.y * rr1[j];
            Ie[j] = py.x * e0[j] + py.y * e1[j];
        }
    } else {
        const int hh = h - S_SZ;
        const float4 wu0 = *reinterpret_cast<const float4*>(Ifw + hh);
        const float4 wu1 = *reinterpret_cast<const float4*>(Ifw + S3 + hh);
        const float4 wu2 = *reinterpret_cast<const float4*>(Ifw + 2 * S3 + hh);
        const float4 wr0 = *reinterpret_cast<const float4*>(Ifw + S_SZ + hh);
        const float4 wr1 = *reinterpret_cast<const float4*>(Ifw + S3 + S_SZ + hh);
        const float4 wr2 = *reinterpret_cast<const float4*>(Ifw + 2 * S3 + S_SZ + hh);
        const float4 we0 = *reinterpret_cast<const float4*>(Ifw + 2 * S_SZ + hh);
        const float4 we1 = *reinterpret_cast<const float4*>(Ifw + S3 + 2 * S_SZ + hh);
        const float4 we2 = *reinterpret_cast<const float4*>(Ifw + 2 * S3 + 2 * S_SZ + hh);
        const float* u0 = &wu0.x; const float* u1 = &wu1.x; const float* u2 = &wu2.x;
        const float* rr0 = &wr0.x; const float* rr1 = &wr1.x; const float* rr2 = &wr2.x;
        const float* e0 = &we0.x; const float* e1 = &we1.x; const float* e2 = &we2.x;
        #pragma unroll
        for (int j = 0; j < 4; ++j) {
            Iu[j] = py.x * u0[j] + py.y * u1[j] + cc * u2[j];
            Ir[j] = py.x * rr0[j] + py.y * rr1[j] + cc * rr2[j];
            Ie[j] = py.x * e0[j] + py.y * e1[j] + cc * e2[j];
        }
    }

    const float4 bu4 = *reinterpret_cast<const float4*>(bu + h);
    const float4 br4 = *reinterpret_cast<const float4*>(br + h);
    const float4 be4 = *reinterpret_cast<const float4*>(be + h);
    float ph[4];
    load4h(Ah + (size_t)b * H_SZ + h, ph);
    const float* bup = &bu4.x; const float* brp = &br4.x; const float* bep = &be4.x;

    float hv[4];
    #pragma unroll
    for (int j = 0; j < 4; ++j) {
        const float u = sigf(Ru[j] + Iu[j] + bup[j]);
        const float r = sigf(Rr[j] + Ir[j] + brp[j]);
        const float e = tanhfast(r * Re[j] + Ie[j] + bep[j]);
        hv[j] = u * ph[j] + (1.0f - u) * e;
    }

    *reinterpret_cast<float4*>(hidden + (size_t)b * H_SZ + h) =
        make_float4(hv[0], hv[1], hv[2], hv[3]);
    __half2* hap = reinterpret_cast<__half2*>(hA + (size_t)b * H_SZ + h);
    hap[0] = __floats2half2_rn(hv[0], hv[1]);
    hap[1] = __floats2half2_rn(hv[2], hv[3]);
}

// ---------------------------------------------------------------------------
// Launch
// ---------------------------------------------------------------------------
extern "C" void kernel_launch(void* const* d_in, const int* in_sizes, int n_in,
                              void* d_out, int out_size)
{
    const float* prev_y  = (const float*)d_in[0];
    const float* prev_h  = (const float*)d_in[1];
    const float* ccoarse = (const float*)d_in[2];
    const float* R_W     = (const float*)d_in[3];
    const float* Icw     = (const float*)d_in[4];
    const float* Ifw     = (const float*)d_in[5];
    const float* O1_W    = (const float*)d_in[6];
    const float* O1_b    = (const float*)d_in[7];
    const float* O2_W    = (const float*)d_in[8];
    const float* O2_b    = (const float*)d_in[9];
    const float* O3_W    = (const float*)d_in[10];
    const float* O3_b    = (const float*)d_in[11];
    const float* O4_W    = (const float*)d_in[12];
    const float* O4_b    = (const float*)d_in[13];
    const float* bu      = (const float*)d_in[14];
    const float* br      = (const float*)d_in[15];
    const float* be      = (const float*)d_in[16];

    float* out        = (float*)d_out;
    float* out_coarse = out;
    float* out_fine   = out + (size_t)B_SZ * Q_SZ;
    float* hidden     = out + (size_t)2 * B_SZ * Q_SZ;

    __half *Rh, *Ah, *hA, *hc, *hf, *RWt, *O1t, *O2t, *O3t, *O4t;
    cudaGetSymbolAddress((void**)&Rh,  g_Rh);
    cudaGetSymbolAddress((void**)&Ah,  g_Ah);
    cudaGetSymbolAddress((void**)&hA,  g_hA);
    cudaGetSymbolAddress((void**)&hc,  g_hc);
    cudaGetSymbolAddress((void**)&hf,  g_hf);
    cudaGetSymbolAddress((void**)&RWt, g_RWt);
    cudaGetSymbolAddress((void**)&O1t, g_O1t);
    cudaGetSymbolAddress((void**)&O2t, g_O2t);
    cudaGetSymbolAddress((void**)&O3t, g_O3t);
    cudaGetSymbolAddress((void**)&O4t, g_O4t);

    const int SMB128 = 2 * (128 + 128) * PW * 4;   // 73728
    const int SMB224 = 2 * (128 + 224) * PW * 4;   // 101376
    cudaFuncSetAttribute(hgemm<128, 0, 1, 0, 2>, cudaFuncAttributeMaxDynamicSharedMemorySize, SMB128);
    cudaFuncSetAttribute(hgemm<224, 1, 1, 1, 1>, cudaFuncAttributeMaxDynamicSharedMemorySize, SMB224);
    cudaFuncSetAttribute(hgemm<128, 2, 0, 1, 2>, cudaFuncAttributeMaxDynamicSharedMemorySize, SMB128);

    // --- prep: ONE launch (f2h + all weight transposes) ---
    prep_all<<<NB_PREP, 256>>>(prev_h, Ah, R_W, RWt,
                               O1_W, O1t, O3_W, O3t, O2_W, O2t, O4_W, O4t);

    const int MT = B_SZ / 128;   // 256 M-tiles

    // 1) Rh = Ah @ RWt^T   (fp16 in, fp16 out)  N=2688=21x128 exact
    hgemm<128, 0, 1, 0, 2><<<dim3(H3 / 128, MT, 1), 256, SMB128>>>(
        Ah, nullptr, H_SZ, RWt, nullptr, H_SZ, nullptr, nullptr,
        Rh, nullptr, H3, H_SZ);
    // 2) GRU gates -> hidden (fp32) + fp16 copy
    gru_elem4<<<(B_SZ * (H_SZ / 4) + 255) / 256, 256>>>(
        Rh, Ah, prev_y, ccoarse, Icw, Ifw, bu, br, be, hidden, hA);
    // 3+4) heads layer 1: N=448=2x224 exact (BN=224, 1 CTA/SM)
    hgemm<224, 1, 1, 1, 1><<<dim3(S_SZ / 224, MT, 2), 256, SMB224>>>(
        hA, hA + S_SZ, H_SZ, O1t, O3t, S_SZ, O1_b, O3_b,
        hc, hf, S_SZ, S_SZ);
    // 5+6) heads layer 2: N=256=2x128 exact
    hgemm<128, 2, 0, 1, 2><<<dim3(Q_SZ / 128, MT, 2), 256, SMB128>>>(
        hc, hf, S_SZ, O2t, O4t, S_SZ, O2_b, O4_b,
        out_coarse, out_fine, Q_SZ, S_SZ);
}

// round 17
// speedup vs baseline: 1.3440x; 1.0004x over previous
#include <cuda_runtime.h>
#include <cuda_fp16.h>
#include <math.h>
#include <stdint.h>

// Problem dims (fixed)
#define B_SZ 32768
#define H_SZ 896
#define S_SZ 448
#define Q_SZ 256
#define H3   2688
#define S3   1344

// ---------------------------------------------------------------------------
// Scratch (device globals; allocation-free per harness rules)
// ---------------------------------------------------------------------------
__device__ __half g_Rh [(size_t)B_SZ * H3];      // R_hidden fp16
__device__ __half g_Ah [(size_t)B_SZ * H_SZ];    // fp16 prev_hidden
__device__ __half g_hA [(size_t)B_SZ * H_SZ];    // fp16 hidden
__device__ __half g_hc [(size_t)B_SZ * S_SZ];
__device__ __half g_hf [(size_t)B_SZ * S_SZ];
__device__ __half g_RWt[(size_t)H3 * H_SZ];
__device__ __half g_O1t[S_SZ * S_SZ];
__device__ __half g_O2t[Q_SZ * S_SZ];
__device__ __half g_O3t[S_SZ * S_SZ];
__device__ __half g_O4t[Q_SZ * S_SZ];

// ---------------------------------------------------------------------------
// Helpers (non-arch-specific PTX only: must assemble for plain sm_103)
// ---------------------------------------------------------------------------
__device__ __forceinline__ uint32_t smem_u32(const void* p) {
    uint32_t a;
    asm("{ .reg .u64 t; cvta.to.shared.u64 t, %1; cvt.u32.u64 %0, t; }" : "=r"(a) : "l"(p));
    return a;
}
__device__ __forceinline__ void cp_async16(uint32_t s, const void* g) {
    asm volatile("cp.async.cg.shared.global [%0], [%1], 16;\n" :: "r"(s), "l"(g));
}
#define CP_COMMIT()  asm volatile("cp.async.commit_group;\n" ::)
#define CP_WAIT(n)   asm volatile("cp.async.wait_group %0;\n" :: "n"(n))

__device__ __forceinline__ void mma_16816(float* d, const uint32_t* a, const uint32_t* b) {
    asm volatile(
        "mma.sync.aligned.m16n8k16.row.col.f32.f16.f16.f32 "
        "{%0,%1,%2,%3}, {%4,%5,%6,%7}, {%8,%9}, {%0,%1,%2,%3};"
        : "+f"(d[0]), "+f"(d[1]), "+f"(d[2]), "+f"(d[3])
        : "r"(a[0]), "r"(a[1]), "r"(a[2]), "r"(a[3]), "r"(b[0]), "r"(b[1]));
}
__device__ __forceinline__ void ldsm4(uint32_t* r, uint32_t addr) {
    asm volatile("ldmatrix.sync.aligned.m8n8.x4.shared.b16 {%0,%1,%2,%3}, [%4];"
                 : "=r"(r[0]), "=r"(r[1]), "=r"(r[2]), "=r"(r[3]) : "r"(addr));
}
__device__ __forceinline__ void ldsm2(uint32_t* r, uint32_t addr) {
    asm volatile("ldmatrix.sync.aligned.m8n8.x2.shared.b16 {%0,%1}, [%2];"
                 : "=r"(r[0]), "=r"(r[1]) : "r"(addr));
}

// ---------------------------------------------------------------------------
// fp16 mma.sync GEMM: C[M,N] = A[M,K] @ Bt[N,K]^T (+bias)(+relu)
// CTA tile 128 x BN (BN divides N exactly, BN % 32 == 0 -> no guards).
// 256 thr = 8 warps (2x4), warp tile 64 x (BN/4). BK=64 fp16.
// SINGLE __syncthreads per mainloop iteration: barrier serves both
// data-visibility (arriving tile) and write-protection (next load issued
// strictly after the barrier).
// EPI: 0=none, 1=bias+relu, 2=bias.  HOUT: 1 = __half C, 0 = float C.
// DUAL: blockIdx.z selects problem set.  MINCTA: launch-bounds min blocks.
// ---------------------------------------------------------------------------
#define PW 36                     // words (4B) per smem row: 64 halves + 16B pad

template <int BN, int EPI, int HOUT, int DUAL, int MINCTA>
__global__ void __launch_bounds__(256, MINCTA)
hgemm(const __half* __restrict__ A0, const __half* __restrict__ A1, int lda,
      const __half* __restrict__ B0, const __half* __restrict__ B1, int ldb,
      const float* __restrict__ bias0, const float* __restrict__ bias1,
      void* __restrict__ C0v, void* __restrict__ C1v, int ldc, int K)
{
    constexpr int AW   = 128 * PW;
    constexpr int BW   = BN * PW;
    constexpr int BUFW = AW + BW;
    constexpr int WN   = BN / 4;          // warp tile N
    constexpr int NF   = BN / 32;         // B n-fragments per warp

    extern __shared__ uint32_t smw[];
    const __half* A    = (DUAL && blockIdx.z) ? A1 : A0;
    const __half* Bt   = (DUAL && blockIdx.z) ? B1 : B0;
    const float*  bias = (DUAL && blockIdx.z) ? bias1 : bias0;
    void*         Cv   = (DUAL && blockIdx.z) ? C1v : C0v;

    const int tid = threadIdx.x;
    const int lane = tid & 31, w = tid >> 5;
    const int wr = w >> 2, wc = w & 3;        // 2x4 warp grid
    const int lq = lane >> 2, ln = lane & 3;

    const int rowBase = blockIdx.y * 128;
    const int colBase = blockIdx.x * BN;

    const uint32_t sBase = smem_u32(smw);

    // cp.async mapping: chunk c = tid + i*256 -> row c>>3 (32/iter), col16 c&7
    const int r0 = tid >> 3, c16 = tid & 7;
    const uint32_t dstOff = (uint32_t)((r0 * PW + c16 * 4) * 4);
    const __half* Abase = A + (size_t)(rowBase + r0) * lda + c16 * 8;
    const __half* Bbase = Bt + (size_t)(colBase + r0) * ldb + c16 * 8;

    auto load_tile = [&](int buf, int it) {
        const int kb = it * 64;
        const uint32_t base = sBase + (uint32_t)(buf * BUFW * 4);
        #pragma unroll
        for (int i = 0; i < 4; ++i)
            cp_async16(base + dstOff + (uint32_t)(i * 32 * PW * 4),
                       Abase + kb + (size_t)(i * 32) * lda);
        #pragma unroll
        for (int i = 0; i < BN * 8 / 256; ++i)
            cp_async16(base + (uint32_t)(AW * 4) + dstOff + (uint32_t)(i * 32 * PW * 4),
                       Bbase + kb + (size_t)(i * 32) * ldb);
        CP_COMMIT();
    };

    // ldmatrix per-lane base offsets (bytes, within buffer)
    const int g = lane >> 3;
    const uint32_t aLB = (uint32_t)((wr * 64 + (lane & 7) + (g & 1) * 8) * PW * 4)
                       + (uint32_t)((g >> 1) * 16);
    const uint32_t bLB = (uint32_t)(AW * 4)
                       + (uint32_t)((wc * WN + (lane & 7) + (g >> 1) * 8) * PW * 4)
                       + (uint32_t)((g & 1) * 16);
    // x2 tail (odd NF): lanes 0-15 supply addresses
    const uint32_t bLB2 = (uint32_t)(AW * 4)
                        + (uint32_t)((wc * WN + (NF - 1) * 8 + (lane & 7)) * PW * 4)
                        + (uint32_t)(((lane >> 3) & 1) * 16);

    float acc[4][NF][4];
    #pragma unroll
    for (int i = 0; i < 4; ++i)
        #pragma unroll
        for (int j = 0; j < NF; ++j)
            #pragma unroll
            for (int k = 0; k < 4; ++k) acc[i][j][k] = 0.0f;

    const int nit = K >> 6;
    load_tile(0, 0);

    for (int it = 0; it < nit; ++it) {
        const int buf = it & 1;
        CP_WAIT(0);           // current tile fully arrived
        __syncthreads();      // + all warps done with buf^1 (prev compute)
        if (it + 1 < nit) load_tile(buf ^ 1, it + 1);   // safe: after barrier

        const uint32_t bufB = sBase + (uint32_t)(buf * BUFW * 4);

        #pragma unroll
        for (int s = 0; s < 4; ++s) {          // 4 x K=16 steps
            uint32_t a[4][4], b[NF][2];
            #pragma unroll
            for (int mf = 0; mf < 4; ++mf)
                ldsm4(a[mf], bufB + aLB + (uint32_t)(mf * 16 * PW * 4) + (uint32_t)(s * 32));
            #pragma unroll
            for (int p = 0; p < NF / 2; ++p) {
                uint32_t t4[4];
                ldsm4(t4, bufB + bLB + (uint32_t)(p * 16 * PW * 4) + (uint32_t)(s * 32));
                b[2 * p][0] = t4[0]; b[2 * p][1] = t4[1];
                b[2 * p + 1][0] = t4[2]; b[2 * p + 1][1] = t4[3];
            }
            if (NF & 1) {
                ldsm2(b[NF - 1], bufB + bLB2 + (uint32_t)(s * 32));
            }
            #pragma unroll
            for (int mf = 0; mf < 4; ++mf)
                #pragma unroll
                for (int nf = 0; nf < NF; ++nf)
                    mma_16816(acc[mf][nf], a[mf], b[nf]);
        }
    }

    // ---- epilogue (exact tiling, no guards) ----
    #pragma unroll
    for (int nf = 0; nf < NF; ++nf) {
        const int col = colBase + wc * WN + nf * 8 + ln * 2;
        float2 bv = make_float2(0.0f, 0.0f);
        if (EPI) bv = *reinterpret_cast<const float2*>(bias + col);
        #pragma unroll
        for (int mf = 0; mf < 4; ++mf) {
            const int row = rowBase + wr * 64 + mf * 16 + lq;
            float2 v0 = make_float2(acc[mf][nf][0], acc[mf][nf][1]);
            float2 v1 = make_float2(acc[mf][nf][2], acc[mf][nf][3]);
            if (EPI) {
                v0.x += bv.x; v0.y += bv.y; v1.x += bv.x; v1.y += bv.y;
                if (EPI == 1) {
                    v0.x = fmaxf(v0.x, 0.0f); v0.y = fmaxf(v0.y, 0.0f);
                    v1.x = fmaxf(v1.x, 0.0f); v1.y = fmaxf(v1.y, 0.0f);
                }
            }
            if (HOUT) {
                __half* Ch = (__half*)Cv;
                *reinterpret_cast<__half2*>(Ch + (size_t)row * ldc + col) =
                    __floats2half2_rn(v0.x, v0.y);
                *reinterpret_cast<__half2*>(Ch + (size_t)(row + 8) * ldc + col) =
                    __floats2half2_rn(v1.x, v1.y);
            } else {
                float* Cf = (float*)Cv;
                *reinterpret_cast<float2*>(Cf + (size_t)row * ldc + col) = v0;
                *reinterpret_cast<float2*>(Cf + (size_t)(row + 8) * ldc + col) = v1;
            }
        }
    }
}

// ---------------------------------------------------------------------------
// Mega-prep: ONE launch. Block-range dispatch.
// ---------------------------------------------------------------------------
#define NB_F2H  (B_SZ * H_SZ / 8 / 256)            // 14336
#define NB_RW   ((H3 / 32) * (H_SZ / 32))          // 2352
#define NB_O13  (2 * (S_SZ / 32) * (S_SZ / 32))    // 392
#define NB_O24  (2 * (Q_SZ / 32) * (S_SZ / 32))    // 224
#define NB_PREP (NB_F2H + NB_RW + NB_O13 + NB_O24)

__device__ __forceinline__ void transpose_body(
    const float* __restrict__ in, __half* __restrict__ out,
    int K, int N, int bx, int by, int tid, float (*t)[33])
{
    const int n0 = bx * 32, k0 = by * 32;
    const int tx = tid & 31, ty = tid >> 5;   // 32 x 8
    #pragma unroll
    for (int j = 0; j < 32; j += 8)
        t[ty + j][tx] = in[(size_t)(k0 + ty + j) * N + n0 + tx];
    __syncthreads();
    #pragma unroll
    for (int j = 0; j < 32; j += 8)
        out[(size_t)(n0 + ty + j) * K + k0 + tx] = __float2half_rn(t[tx][ty + j]);
}

__global__ void __launch_bounds__(256)
prep_all(const float* __restrict__ prev_h, __half* __restrict__ Ah,
         const float* __restrict__ R_W,  __half* __restrict__ RWt,
         const float* __restrict__ O1_W, __half* __restrict__ O1t,
         const float* __restrict__ O3_W, __half* __restrict__ O3t,
         const float* __restrict__ O2_W, __half* __restrict__ O2t,
         const float* __restrict__ O4_W, __half* __restrict__ O4t)
{
    __shared__ float t[32][33];
    const int tid = threadIdx.x;
    int b = blockIdx.x;

    if (b < NB_F2H) {
        const int i = b * 256 + tid;
        const float4* in = (const float4*)prev_h;
        __half2* out = (__half2*)Ah;
        float4 v0 = in[2 * i], v1 = in[2 * i + 1];
        out[4 * i]     = __floats2half2_rn(v0.x, v0.y);
        out[4 * i + 1] = __floats2half2_rn(v0.z, v0.w);
        out[4 * i + 2] = __floats2half2_rn(v1.x, v1.y);
        out[4 * i + 3] = __floats2half2_rn(v1.z, v1.w);
        return;
    }
    b -= NB_F2H;
    if (b < NB_RW) {
        transpose_body(R_W, RWt, H_SZ, H3, b % (H3 / 32), b / (H3 / 32), tid, t);
        return;
    }
    b -= NB_RW;
    if (b < NB_O13) {
        const int half = NB_O13 / 2;
        const float* in  = (b < half) ? O1_W : O3_W;
        __half*      out = (b < half) ? O1t  : O3t;
        const int bb = (b < half) ? b : b - half;
        transpose_body(in, out, S_SZ, S_SZ, bb % (S_SZ / 32), bb / (S_SZ / 32), tid, t);
        return;
    }
    b -= NB_O13;
    {
        const int half = NB_O24 / 2;
        const float* in  = (b < half) ? O2_W : O4_W;
        __half*      out = (b < half) ? O2t  : O4t;
        const int bb = (b < half) ? b : b - half;
        transpose_body(in, out, S_SZ, Q_SZ, bb % (Q_SZ / 32), bb / (Q_SZ / 32), tid, t);
    }
}

// ---------------------------------------------------------------------------
// GRU gate elementwise, 4 h per thread; prev_h read as fp16 (Ah)
// ---------------------------------------------------------------------------
__device__ __forceinline__ void load4h(const __half* p, float* o) {
    const __half2 v0 = *reinterpret_cast<const __half2*>(p);
    const __half2 v1 = *reinterpret_cast<const __half2*>(p + 2);
    const float2 f0 = __half22float2(v0), f1 = __half22float2(v1);
    o[0] = f0.x; o[1] = f0.y; o[2] = f1.x; o[3] = f1.y;
}
__device__ __forceinline__ float sigf(float x) {
    return 1.0f / (1.0f + __expf(-x));
}
__device__ __forceinline__ float tanhfast(float x) {
    return 2.0f / (1.0f + __expf(-2.0f * x)) - 1.0f;
}

__global__ void gru_elem4(const __half* __restrict__ Rh, const __half* __restrict__ Ah,
                          const float* __restrict__ prev_y, const float* __restrict__ ccoarse,
                          const float* __restrict__ Icw, const float* __restrict__ Ifw,
                          const float* __restrict__ bu, const float* __restrict__ br,
                          const float* __restrict__ be,
                          float* __restrict__ hidden, __half* __restrict__ hA) {
    const int idx = blockIdx.x * blockDim.x + threadIdx.x;
    if (idx >= B_SZ * (H_SZ / 4)) return;
    const int b = idx / (H_SZ / 4);
    const int h = (idx - b * (H_SZ / 4)) * 4;

    const float2 py = *reinterpret_cast<const float2*>(prev_y + 2 * b);
    const float cc = ccoarse[b];

    const __half* r0 = Rh + (size_t)b * H3;
    float Ru[4], Rr[4], Re[4];
    load4h(r0 + h, Ru);
    load4h(r0 + H_SZ + h, Rr);
    load4h(r0 + 2 * H_SZ + h, Re);

    float Iu[4], Ir[4], Ie[4];
    if (h < S_SZ) {
        const float4 wu0 = *reinterpret_cast<const float4*>(Icw + h);
        const float4 wu1 = *reinterpret_cast<const float4*>(Icw + S3 + h);
        const float4 wr0 = *reinterpret_cast<const float4*>(Icw + S_SZ + h);
        const float4 wr1 = *reinterpret_cast<const float4*>(Icw + S3 + S_SZ + h);
        const float4 we0 = *reinterpret_cast<const float4*>(Icw + 2 * S_SZ + h);
        const float4 we1 = *reinterpret_cast<const float4*>(Icw + S3 + 2 * S_SZ + h);
        const float* u0 = &wu0.x; const float* u1 = &wu1.x;
        const float* rr0 = &wr0.x; const float* rr1 = &wr1.x;
        const float* e0 = &we0.x; const float* e1 = &we1.x;
        #pragma unroll
        for (int j = 0; j < 4; ++j) {
            Iu[j] = py.x * u0[j] + py.y * u1[j];
            Ir[j] = py.x * rr0[j] + py.y * rr1[j];
            Ie[j] = py.x * e0[j] + py.y * e1[j];
        }
    } else {
        const int hh = h - S_SZ;
        const float4 wu0 = *reinterpret_cast<const float4*>(Ifw + hh);
        const float4 wu1 = *reinterpret_cast<const float4*>(Ifw + S3 + hh);
        const float4 wu2 = *reinterpret_cast<const float4*>(Ifw + 2 * S3 + hh);
        const float4 wr0 = *reinterpret_cast<const float4*>(Ifw + S_SZ + hh);
        const float4 wr1 = *reinterpret_cast<const float4*>(Ifw + S3 + S_SZ + hh);
        const float4 wr2 = *reinterpret_cast<const float4*>(Ifw + 2 * S3 + S_SZ + hh);
        const float4 we0 = *reinterpret_cast<const float4*>(Ifw + 2 * S_SZ + hh);
        const float4 we1 = *reinterpret_cast<const float4*>(Ifw + S3 + 2 * S_SZ + hh);
        const float4 we2 = *reinterpret_cast<const float4*>(Ifw + 2 * S3 + 2 * S_SZ + hh);
        const float* u0 = &wu0.x; const float* u1 = &wu1.x; const float* u2 = &wu2.x;
        const float* rr0 = &wr0.x; const float* rr1 = &wr1.x; const float* rr2 = &wr2.x;
        const float* e0 = &we0.x; const float* e1 = &we1.x; const float* e2 = &we2.x;
        #pragma unroll
        for (int j = 0; j < 4; ++j) {
            Iu[j] = py.x * u0[j] + py.y * u1[j] + cc * u2[j];
            Ir[j] = py.x * rr0[j] + py.y * rr1[j] + cc * rr2[j];
            Ie[j] = py.x * e0[j] + py.y * e1[j] + cc * e2[j];
        }
    }

    const float4 bu4 = *reinterpret_cast<const float4*>(bu + h);
    const float4 br4 = *reinterpret_cast<const float4*>(br + h);
    const float4 be4 = *reinterpret_cast<const float4*>(be + h);
    float ph[4];
    load4h(Ah + (size_t)b * H_SZ + h, ph);
    const float* bup = &bu4.x; const float* brp = &br4.x; const float* bep = &be4.x;

    float hv[4];
    #pragma unroll
    for (int j = 0; j < 4; ++j) {
        const float u = sigf(Ru[j] + Iu[j] + bup[j]);
        const float r = sigf(Rr[j] + Ir[j] + brp[j]);
        const float e = tanhfast(r * Re[j] + Ie[j] + bep[j]);
        hv[j] = u * ph[j] + (1.0f - u) * e;
    }

    *reinterpret_cast<float4*>(hidden + (size_t)b * H_SZ + h) =
        make_float4(hv[0], hv[1], hv[2], hv[3]);
    __half2* hap = reinterpret_cast<__half2*>(hA + (size_t)b * H_SZ + h);
    hap[0] = __floats2half2_rn(hv[0], hv[1]);
    hap[1] = __floats2half2_rn(hv[2], hv[3]);
}

// ---------------------------------------------------------------------------
// Launch
// ---------------------------------------------------------------------------
extern "C" void kernel_launch(void* const* d_in, const int* in_sizes, int n_in,
                              void* d_out, int out_size)
{
    const float* prev_y  = (const float*)d_in[0];
    const float* prev_h  = (const float*)d_in[1];
    const float* ccoarse = (const float*)d_in[2];
    const float* R_W     = (const float*)d_in[3];
    const float* Icw     = (const float*)d_in[4];
    const float* Ifw     = (const float*)d_in[5];
    const float* O1_W    = (const float*)d_in[6];
    const float* O1_b    = (const float*)d_in[7];
    const float* O2_W    = (const float*)d_in[8];
    const float* O2_b    = (const float*)d_in[9];
    const float* O3_W    = (const float*)d_in[10];
    const float* O3_b    = (const float*)d_in[11];
    const float* O4_W    = (const float*)d_in[12];
    const float* O4_b    = (const float*)d_in[13];
    const float* bu      = (const float*)d_in[14];
    const float* br      = (const float*)d_in[15];
    const float* be      = (const float*)d_in[16];

    float* out        = (float*)d_out;
    float* out_coarse = out;
    float* out_fine   = out + (size_t)B_SZ * Q_SZ;
    float* hidden     = out + (size_t)2 * B_SZ * Q_SZ;

    __half *Rh, *Ah, *hA, *hc, *hf, *RWt, *O1t, *O2t, *O3t, *O4t;
    cudaGetSymbolAddress((void**)&Rh,  g_Rh);
    cudaGetSymbolAddress((void**)&Ah,  g_Ah);
    cudaGetSymbolAddress((void**)&hA,  g_hA);
    cudaGetSymbolAddress((void**)&hc,  g_hc);
    cudaGetSymbolAddress((void**)&hf,  g_hf);
    cudaGetSymbolAddress((void**)&RWt, g_RWt);
    cudaGetSymbolAddress((void**)&O1t, g_O1t);
    cudaGetSymbolAddress((void**)&O2t, g_O2t);
    cudaGetSymbolAddress((void**)&O3t, g_O3t);
    cudaGetSymbolAddress((void**)&O4t, g_O4t);

    const int SMB128 = 2 * (128 + 128) * PW * 4;   // 73728
    const int SMB224 = 2 * (128 + 224) * PW * 4;   // 101376
    cudaFuncSetAttribute(hgemm<128, 0, 1, 0, 2>, cudaFuncAttributeMaxDynamicSharedMemorySize, SMB128);
    cudaFuncSetAttribute(hgemm<224, 1, 1, 1, 1>, cudaFuncAttributeMaxDynamicSharedMemorySize, SMB224);
    cudaFuncSetAttribute(hgemm<128, 2, 0, 1, 2>, cudaFuncAttributeMaxDynamicSharedMemorySize, SMB128);

    // --- prep: ONE launch (f2h + all weight transposes) ---
    prep_all<<<NB_PREP, 256>>>(prev_h, Ah, R_W, RWt,
                               O1_W, O1t, O3_W, O3t, O2_W, O2t, O4_W, O4t);

    const int MT = B_SZ / 128;   // 256 M-tiles

    // 1) Rh = Ah @ RWt^T   (fp16 in, fp16 out)  N=2688=21x128 exact
    hgemm<128, 0, 1, 0, 2><<<dim3(H3 / 128, MT, 1), 256, SMB128>>>(
        Ah, nullptr, H_SZ, RWt, nullptr, H_SZ, nullptr, nullptr,
        Rh, nullptr, H3, H_SZ);
    // 2) GRU gates -> hidden (fp32) + fp16 copy
    gru_elem4<<<(B_SZ * (H_SZ / 4) + 255) / 256, 256>>>(
        Rh, Ah, prev_y, ccoarse, Icw, Ifw, bu, br, be, hidden, hA);
    // 3+4) heads layer 1: N=448=2x224 exact (BN=224, 1 CTA/SM)
    hgemm<224, 1, 1, 1, 1><<<dim3(S_SZ / 224, MT, 2), 256, SMB224>>>(
        hA, hA + S_SZ, H_SZ, O1t, O3t, S_SZ, O1_b, O3_b,
        hc, hf, S_SZ, S_SZ);
    // 5+6) heads layer 2: N=256=2x128 exact
    hgemm<128, 2, 0, 1, 2><<<dim3(Q_SZ / 128, MT, 2), 256, SMB128>>>(
        hc, hf, S_SZ, O2t, O4t, S_SZ, O2_b, O4_b,
        out_coarse, out_fine, Q_SZ, S_SZ);
}